// round 6
// baseline (speedup 1.0000x reference)
#include <cuda_runtime.h>
#include <cuda_bf16.h>
#include <math.h>

typedef unsigned long long ull;

#define Bb 4
#define Nn 2048
#define Dd 768
#define Hh 6
#define Do_ 128

__device__ __align__(16) float g_h[Bb*Nn*Dd];     // per-head projected features, col = h*128+o
__device__ __align__(16) float g_gate[Bb*Nn*Dd];  // sigmoid gate
__device__ float g_src[Bb*Hh*Nn];
__device__ float g_dst[Bb*Hh*Nn];
__device__ float g_M[Bb*Hh*Nn];                   // leaky(src_i + max_j dst_j)

// ---------- packed f32x2 helpers ----------
__device__ __forceinline__ ull pk2(float x) {
    ull r; asm("mov.b64 %0, {%1, %2};" : "=l"(r) : "f"(x), "f"(x)); return r;
}
__device__ __forceinline__ ull f2(ull a, ull b, ull c) {
    ull d; asm("fma.rn.f32x2 %0, %1, %2, %3;" : "=l"(d) : "l"(a), "l"(b), "l"(c)); return d;
}
__device__ __forceinline__ float lo32(ull v) { return __uint_as_float((unsigned)(v & 0xffffffffull)); }
__device__ __forceinline__ float hi32(ull v) { return __uint_as_float((unsigned)(v >> 32)); }
__device__ __forceinline__ float sigm(float x) { return 1.0f / (1.0f + __expf(-x)); }

// =========================================================================
// Kernel 1: dual GEMM. A = X [8192 x 768]. Global cols 0..767 -> h (B from W),
// cols 768..1535 -> gate (B = H_w rows, NT access). BM=128 BN=64 BK=16,
// 256 threads, thread tile 8 rows x 4 cols (2 f32x2 pairs).
// =========================================================================
__global__ __launch_bounds__(256) void proj_gemm(
    const float* __restrict__ X, const float* __restrict__ W,
    const float* __restrict__ Hw, const float* __restrict__ Hb)
{
    __shared__ __align__(16) float As[16][128];
    __shared__ __align__(16) float Bs[16][64];

    const int tid   = threadIdx.x;
    const int cBase = blockIdx.x * 64;        // 0..1472
    const bool isGate = (cBase >= 768);
    const int m0    = blockIdx.y * 128;

    const int aRow = tid >> 2;                // 0..63
    const int aKq  = tid & 3;                 // k-quad

    int bK, bC;
    const float* Bptr;
    if (!isGate) {
        bK = tid >> 4; bC = tid & 15;
        Bptr = W + (size_t)(cBase >> 7) * (768*128) + (cBase & 127);
    } else {
        bC = tid >> 2; bK = tid & 3;
        Bptr = Hw + (size_t)(cBase - 768 + bC) * 768;
    }

    float4 aR0, aR1, bR;
    aR0 = *(const float4*)(X + (size_t)(m0 + aRow) * 768 + aKq*4);
    aR1 = *(const float4*)(X + (size_t)(m0 + 64 + aRow) * 768 + aKq*4);
    if (!isGate) bR = *(const float4*)(Bptr + (size_t)bK * 128 + bC*4);
    else         bR = *(const float4*)(Bptr + bK*4);

    const int ty = tid >> 4, tx = tid & 15;
    ull acc[8][2];
    #pragma unroll
    for (int i = 0; i < 8; i++) { acc[i][0] = 0ull; acc[i][1] = 0ull; }

    for (int kt = 0; kt < 48; kt++) {
        __syncthreads();
        As[aKq*4+0][aRow] = aR0.x; As[aKq*4+1][aRow] = aR0.y;
        As[aKq*4+2][aRow] = aR0.z; As[aKq*4+3][aRow] = aR0.w;
        As[aKq*4+0][64+aRow] = aR1.x; As[aKq*4+1][64+aRow] = aR1.y;
        As[aKq*4+2][64+aRow] = aR1.z; As[aKq*4+3][64+aRow] = aR1.w;
        if (!isGate) { *(float4*)&Bs[bK][bC*4] = bR; }
        else { Bs[bK*4+0][bC] = bR.x; Bs[bK*4+1][bC] = bR.y;
               Bs[bK*4+2][bC] = bR.z; Bs[bK*4+3][bC] = bR.w; }
        __syncthreads();
        if (kt < 47) {  // prefetch next slab while computing this one
            const int k0 = (kt + 1) * 16;
            aR0 = *(const float4*)(X + (size_t)(m0 + aRow) * 768 + k0 + aKq*4);
            aR1 = *(const float4*)(X + (size_t)(m0 + 64 + aRow) * 768 + k0 + aKq*4);
            if (!isGate) bR = *(const float4*)(Bptr + (size_t)(k0 + bK) * 128 + bC*4);
            else         bR = *(const float4*)(Bptr + k0 + bK*4);
        }
        #pragma unroll 4
        for (int k = 0; k < 16; k++) {
            const float4 a0 = *(const float4*)&As[k][ty*8];
            const float4 a1 = *(const float4*)&As[k][ty*8+4];
            const ulonglong2 bv = *(const ulonglong2*)&Bs[k][tx*4];
            ull q;
            q = pk2(a0.x); acc[0][0]=f2(q,bv.x,acc[0][0]); acc[0][1]=f2(q,bv.y,acc[0][1]);
            q = pk2(a0.y); acc[1][0]=f2(q,bv.x,acc[1][0]); acc[1][1]=f2(q,bv.y,acc[1][1]);
            q = pk2(a0.z); acc[2][0]=f2(q,bv.x,acc[2][0]); acc[2][1]=f2(q,bv.y,acc[2][1]);
            q = pk2(a0.w); acc[3][0]=f2(q,bv.x,acc[3][0]); acc[3][1]=f2(q,bv.y,acc[3][1]);
            q = pk2(a1.x); acc[4][0]=f2(q,bv.x,acc[4][0]); acc[4][1]=f2(q,bv.y,acc[4][1]);
            q = pk2(a1.y); acc[5][0]=f2(q,bv.x,acc[5][0]); acc[5][1]=f2(q,bv.y,acc[5][1]);
            q = pk2(a1.z); acc[6][0]=f2(q,bv.x,acc[6][0]); acc[6][1]=f2(q,bv.y,acc[6][1]);
            q = pk2(a1.w); acc[7][0]=f2(q,bv.x,acc[7][0]); acc[7][1]=f2(q,bv.y,acc[7][1]);
        }
    }

    if (!isGate) {
        const int c = cBase + tx*4;
        #pragma unroll
        for (int i = 0; i < 8; i++) {
            const int row = m0 + ty*8 + i;
            float4 o;
            o.x = lo32(acc[i][0]); o.y = hi32(acc[i][0]);
            o.z = lo32(acc[i][1]); o.w = hi32(acc[i][1]);
            *(float4*)(g_h + (size_t)row * 768 + c) = o;
        }
    } else {
        const int cg = cBase - 768 + tx*4;
        const float4 hb = *(const float4*)(Hb + cg);
        #pragma unroll
        for (int i = 0; i < 8; i++) {
            const int row = m0 + ty*8 + i;
            float4 o;
            o.x = sigm(lo32(acc[i][0]) + hb.x);
            o.y = sigm(hi32(acc[i][0]) + hb.y);
            o.z = sigm(lo32(acc[i][1]) + hb.z);
            o.w = sigm(hi32(acc[i][1]) + hb.w);
            *(float4*)(g_gate + (size_t)row * 768 + cg) = o;
        }
    }
}

// =========================================================================
// Kernel 2: src/dst = <tanh(h[b,h,n,:]), w_src/w_dst>. One warp per row.
// =========================================================================
__global__ __launch_bounds__(256) void srcdst_kernel(
    const float* __restrict__ wsrc, const float* __restrict__ wdst)
{
    const int tid = threadIdx.x, lane = tid & 31, wid = tid >> 5;
    const int gid = blockIdx.x * 8 + wid;          // 0..49151
    const int b = gid / 12288;
    const int r = gid - b * 12288;
    const int h = r >> 11;
    const int n = r & 2047;

    const float4 v  = *(const float4*)(g_h + (size_t)(b*2048 + n)*768 + h*128 + lane*4);
    const float4 ws = *(const float4*)(wsrc + h*128 + lane*4);
    const float4 wd = *(const float4*)(wdst + h*128 + lane*4);
    float t, ss = 0.f, sd = 0.f;
    t = tanhf(v.x); ss += t*ws.x; sd += t*wd.x;
    t = tanhf(v.y); ss += t*ws.y; sd += t*wd.y;
    t = tanhf(v.z); ss += t*ws.z; sd += t*wd.z;
    t = tanhf(v.w); ss += t*ws.w; sd += t*wd.w;
    #pragma unroll
    for (int o = 16; o > 0; o >>= 1) {
        ss += __shfl_xor_sync(0xffffffffu, ss, o);
        sd += __shfl_xor_sync(0xffffffffu, sd, o);
    }
    if (lane == 0) {
        const int idx = (b*6 + h)*2048 + n;
        g_src[idx] = ss; g_dst[idx] = sd;
    }
}

// =========================================================================
// Kernel 3: M[b,h,i] = leaky(src[i] + max_j dst[j]). One block per (b,h).
// leaky is monotone, so this upper-bounds every unmasked score.
// =========================================================================
__global__ __launch_bounds__(256) void rowmax_kernel()
{
    __shared__ float red[256];
    const int bh = blockIdx.x, tid = threadIdx.x;
    float m = -3.0e38f;
    for (int n = tid; n < 2048; n += 256) m = fmaxf(m, g_dst[bh*2048 + n]);
    red[tid] = m; __syncthreads();
    for (int s = 128; s > 0; s >>= 1) {
        if (tid < s) red[tid] = fmaxf(red[tid], red[tid + s]);
        __syncthreads();
    }
    const float mx = red[0];
    for (int n = tid; n < 2048; n += 256) {
        float s = g_src[bh*2048 + n] + mx;
        g_M[bh*2048 + n] = (s < 0.f) ? 0.2f * s : s;
    }
}

// =========================================================================
// Kernel 4: fused attention. Block = (64-row i-tile, h, b), 128 threads.
// Per 32-j tile: stage V + build masked-exp P in smem, then register-tiled
// P@V (8x8 per thread, f32x2). Epilogue: /l, +bias, ELU, gate residual.
// =========================================================================
__global__ __launch_bounds__(128) void attn_kernel(
    const float* __restrict__ feat_in, const int* __restrict__ adj,
    const float* __restrict__ bias, float* __restrict__ out)
{
    __shared__ __align__(16) float Vs[32][132];   // 132: keep rows 16B-aligned (528B)
    __shared__ __align__(16) float Ps[32][64];
    __shared__ float sDst[2048];
    __shared__ float sSrc[64];
    __shared__ float sM[64];
    __shared__ float sLinv[64];
    __shared__ float lpart[2][64];

    const int tid = threadIdx.x;
    const int b = blockIdx.z, h = blockIdx.y;
    const int i0 = blockIdx.x * 64;
    const int bh = b*6 + h;

    for (int t = tid; t < 2048; t += 128) sDst[t] = g_dst[bh*2048 + t];
    if (tid < 64) {
        sSrc[tid] = g_src[bh*2048 + i0 + tid];
        sM[tid]   = g_M[bh*2048 + i0 + tid];
    }
    __syncthreads();

    const int il = tid & 63, jh = tid >> 6;        // P role: row il, j-half jh
    const float srcv = sSrc[il], Mv = sM[il];
    float psum = 0.f;
    const int ty = tid >> 4, tx = tid & 15;        // GEMM role: 8 rows x 8 cols
    const int vj = tid >> 2, vq = tid & 3;         // V-loader role

    const float* Vg = g_h + (size_t)(b*2048)*768 + h*128;
    const int* adjRow = adj + ((size_t)b*2048 + (i0 + il)) * 2048;

    ull acc[8][4];
    #pragma unroll
    for (int i = 0; i < 8; i++)
        #pragma unroll
        for (int q = 0; q < 4; q++) acc[i][q] = 0ull;

    for (int jt = 0; jt < 64; jt++) {
        const int j0 = jt * 32;

        // V tile: row vj, cols vq*32..vq*32+31
        #pragma unroll
        for (int k = 0; k < 8; k++) {
            float4 v = *(const float4*)(Vg + (size_t)(j0 + vj)*768 + vq*32 + k*4);
            *(float4*)&Vs[vj][vq*32 + k*4] = v;
        }

        // P tile: this thread covers j = j0 + jh*16 + (0..15)
        #pragma unroll
        for (int q = 0; q < 4; q++) {
            const int jb = jh*16 + q*4;
            const int4 a4 = *(const int4*)(adjRow + j0 + jb);
            float s, p;
            s = srcv + sDst[j0 + jb + 0]; s = (s < 0.f) ? 0.2f*s : s;
            p = a4.x ? __expf(s - Mv) : 0.f; psum += p; Ps[jb + 0][il] = p;
            s = srcv + sDst[j0 + jb + 1]; s = (s < 0.f) ? 0.2f*s : s;
            p = a4.y ? __expf(s - Mv) : 0.f; psum += p; Ps[jb + 1][il] = p;
            s = srcv + sDst[j0 + jb + 2]; s = (s < 0.f) ? 0.2f*s : s;
            p = a4.z ? __expf(s - Mv) : 0.f; psum += p; Ps[jb + 2][il] = p;
            s = srcv + sDst[j0 + jb + 3]; s = (s < 0.f) ? 0.2f*s : s;
            p = a4.w ? __expf(s - Mv) : 0.f; psum += p; Ps[jb + 3][il] = p;
        }
        __syncthreads();

        // register-tiled P@V
        #pragma unroll 4
        for (int j = 0; j < 32; j++) {
            const float4 p0 = *(const float4*)&Ps[j][ty*8];
            const float4 p1 = *(const float4*)&Ps[j][ty*8 + 4];
            const ulonglong2 vA = *(const ulonglong2*)&Vs[j][tx*8];
            const ulonglong2 vB = *(const ulonglong2*)&Vs[j][tx*8 + 4];
            ull q;
            q = pk2(p0.x); acc[0][0]=f2(q,vA.x,acc[0][0]); acc[0][1]=f2(q,vA.y,acc[0][1]);
                           acc[0][2]=f2(q,vB.x,acc[0][2]); acc[0][3]=f2(q,vB.y,acc[0][3]);
            q = pk2(p0.y); acc[1][0]=f2(q,vA.x,acc[1][0]); acc[1][1]=f2(q,vA.y,acc[1][1]);
                           acc[1][2]=f2(q,vB.x,acc[1][2]); acc[1][3]=f2(q,vB.y,acc[1][3]);
            q = pk2(p0.z); acc[2][0]=f2(q,vA.x,acc[2][0]); acc[2][1]=f2(q,vA.y,acc[2][1]);
                           acc[2][2]=f2(q,vB.x,acc[2][2]); acc[2][3]=f2(q,vB.y,acc[2][3]);
            q = pk2(p0.w); acc[3][0]=f2(q,vA.x,acc[3][0]); acc[3][1]=f2(q,vA.y,acc[3][1]);
                           acc[3][2]=f2(q,vB.x,acc[3][2]); acc[3][3]=f2(q,vB.y,acc[3][3]);
            q = pk2(p1.x); acc[4][0]=f2(q,vA.x,acc[4][0]); acc[4][1]=f2(q,vA.y,acc[4][1]);
                           acc[4][2]=f2(q,vB.x,acc[4][2]); acc[4][3]=f2(q,vB.y,acc[4][3]);
            q = pk2(p1.y); acc[5][0]=f2(q,vA.x,acc[5][0]); acc[5][1]=f2(q,vA.y,acc[5][1]);
                           acc[5][2]=f2(q,vB.x,acc[5][2]); acc[5][3]=f2(q,vB.y,acc[5][3]);
            q = pk2(p1.z); acc[6][0]=f2(q,vA.x,acc[6][0]); acc[6][1]=f2(q,vA.y,acc[6][1]);
                           acc[6][2]=f2(q,vB.x,acc[6][2]); acc[6][3]=f2(q,vB.y,acc[6][3]);
            q = pk2(p1.w); acc[7][0]=f2(q,vA.x,acc[7][0]); acc[7][1]=f2(q,vA.y,acc[7][1]);
                           acc[7][2]=f2(q,vB.x,acc[7][2]); acc[7][3]=f2(q,vB.y,acc[7][3]);
        }
        __syncthreads();
    }

    // softmax denominators
    lpart[jh][il] = psum;
    __syncthreads();
    if (tid < 64) sLinv[tid] = 1.0f / (lpart[0][tid] + lpart[1][tid]);
    __syncthreads();

    // epilogue: /l + bias, ELU, gated residual with feat_in
    const float4 bv0 = *(const float4*)(bias + tx*8);
    const float4 bv1 = *(const float4*)(bias + tx*8 + 4);
    #pragma unroll
    for (int i = 0; i < 8; i++) {
        const int row = ty*8 + i;
        const int n = i0 + row;
        const float linv = sLinv[row];
        const size_t base = ((size_t)(b*2048) + n)*768 + h*128 + tx*8;
        const float4 x0 = *(const float4*)(feat_in + base);
        const float4 x1 = *(const float4*)(feat_in + base + 4);
        const float4 g0 = *(const float4*)(g_gate + base);
        const float4 g1 = *(const float4*)(g_gate + base + 4);
        float fo, e;
        float4 o0, o1;
        fo = lo32(acc[i][0])*linv + bv0.x; e = (fo > 0.f) ? fo : expm1f(fo); o0.x = x0.x + g0.x*(e - x0.x);
        fo = hi32(acc[i][0])*linv + bv0.y; e = (fo > 0.f) ? fo : expm1f(fo); o0.y = x0.y + g0.y*(e - x0.y);
        fo = lo32(acc[i][1])*linv + bv0.z; e = (fo > 0.f) ? fo : expm1f(fo); o0.z = x0.z + g0.z*(e - x0.z);
        fo = hi32(acc[i][1])*linv + bv0.w; e = (fo > 0.f) ? fo : expm1f(fo); o0.w = x0.w + g0.w*(e - x0.w);
        fo = lo32(acc[i][2])*linv + bv1.x; e = (fo > 0.f) ? fo : expm1f(fo); o1.x = x1.x + g1.x*(e - x1.x);
        fo = hi32(acc[i][2])*linv + bv1.y; e = (fo > 0.f) ? fo : expm1f(fo); o1.y = x1.y + g1.y*(e - x1.y);
        fo = lo32(acc[i][3])*linv + bv1.z; e = (fo > 0.f) ? fo : expm1f(fo); o1.z = x1.z + g1.z*(e - x1.z);
        fo = hi32(acc[i][3])*linv + bv1.w; e = (fo > 0.f) ? fo : expm1f(fo); o1.w = x1.w + g1.w*(e - x1.w);
        *(float4*)(out + base)     = o0;
        *(float4*)(out + base + 4) = o1;
    }
}

extern "C" void kernel_launch(void* const* d_in, const int* in_sizes, int n_in,
                              void* d_out, int out_size) {
    (void)in_sizes; (void)n_in; (void)out_size;
    const float* feat_in = (const float*)d_in[0];
    const int*   adj     = (const int*)d_in[1];
    const float* W       = (const float*)d_in[2];
    const float* bvec    = (const float*)d_in[3];
    const float* w_src   = (const float*)d_in[4];
    const float* w_dst   = (const float*)d_in[5];
    const float* H_w     = (const float*)d_in[6];
    const float* H_b     = (const float*)d_in[7];
    float* out = (float*)d_out;

    proj_gemm<<<dim3(24, 64), 256>>>(feat_in, W, H_w, H_b);
    srcdst_kernel<<<6144, 256>>>(w_src, w_dst);
    rowmax_kernel<<<24, 256>>>();
    attn_kernel<<<dim3(32, 6, 4), 128>>>(feat_in, adj, bvec, out);
}

// round 10
// speedup vs baseline: 1.2227x; 1.2227x over previous
#include <cuda_runtime.h>
#include <cuda_bf16.h>
#include <math.h>

typedef unsigned long long ull;

#define Bb 4
#define Nn 2048
#define Dd 768
#define Hh 6
#define Do_ 128

__device__ __align__(16) float g_h[Bb*Nn*Dd];     // per-head projected features, col = h*128+o
__device__ __align__(16) float g_gate[Bb*Nn*Dd];  // sigmoid gate
__device__ float g_src[Bb*Hh*Nn];
__device__ float g_dst[Bb*Hh*Nn];
__device__ float g_M[Bb*Hh*Nn];                   // leaky(src_i + max_j dst_j)
__device__ unsigned g_adjbits[Bb*64*Nn];          // transposed bitmask: [b][word(j/32)][n]

// ---------- packed f32x2 helpers ----------
__device__ __forceinline__ ull pk2(float x) {
    ull r; asm("mov.b64 %0, {%1, %2};" : "=l"(r) : "f"(x), "f"(x)); return r;
}
__device__ __forceinline__ ull f2(ull a, ull b, ull c) {
    ull d; asm("fma.rn.f32x2 %0, %1, %2, %3;" : "=l"(d) : "l"(a), "l"(b), "l"(c)); return d;
}
__device__ __forceinline__ float lo32(ull v) { return __uint_as_float((unsigned)(v & 0xffffffffull)); }
__device__ __forceinline__ float hi32(ull v) { return __uint_as_float((unsigned)(v >> 32)); }
__device__ __forceinline__ float sigm(float x) { return 1.0f / (1.0f + __expf(-x)); }

// =========================================================================
// Kernel 1: dual GEMM. A = X [8192 x 768]. Global cols 0..767 -> h (B from W),
// cols 768..1535 -> gate (B = H_w rows, NT access). BM=128 BN=64 BK=16,
// 256 threads, thread tile 8 rows x 4 cols (2 f32x2 pairs).
// =========================================================================
__global__ __launch_bounds__(256) void proj_gemm(
    const float* __restrict__ X, const float* __restrict__ W,
    const float* __restrict__ Hw, const float* __restrict__ Hb)
{
    __shared__ __align__(16) float As[16][128];
    __shared__ __align__(16) float Bs[16][64];

    const int tid   = threadIdx.x;
    const int cBase = blockIdx.x * 64;        // 0..1472
    const bool isGate = (cBase >= 768);
    const int m0    = blockIdx.y * 128;

    const int aRow = tid >> 2;                // 0..63
    const int aKq  = tid & 3;                 // k-quad

    int bK, bC;
    const float* Bptr;
    if (!isGate) {
        bK = tid >> 4; bC = tid & 15;
        Bptr = W + (size_t)(cBase >> 7) * (768*128) + (cBase & 127);
    } else {
        bC = tid >> 2; bK = tid & 3;
        Bptr = Hw + (size_t)(cBase - 768 + bC) * 768;
    }

    float4 aR0, aR1, bR;
    aR0 = *(const float4*)(X + (size_t)(m0 + aRow) * 768 + aKq*4);
    aR1 = *(const float4*)(X + (size_t)(m0 + 64 + aRow) * 768 + aKq*4);
    if (!isGate) bR = *(const float4*)(Bptr + (size_t)bK * 128 + bC*4);
    else         bR = *(const float4*)(Bptr + bK*4);

    const int ty = tid >> 4, tx = tid & 15;
    ull acc[8][2];
    #pragma unroll
    for (int i = 0; i < 8; i++) { acc[i][0] = 0ull; acc[i][1] = 0ull; }

    for (int kt = 0; kt < 48; kt++) {
        __syncthreads();
        As[aKq*4+0][aRow] = aR0.x; As[aKq*4+1][aRow] = aR0.y;
        As[aKq*4+2][aRow] = aR0.z; As[aKq*4+3][aRow] = aR0.w;
        As[aKq*4+0][64+aRow] = aR1.x; As[aKq*4+1][64+aRow] = aR1.y;
        As[aKq*4+2][64+aRow] = aR1.z; As[aKq*4+3][64+aRow] = aR1.w;
        if (!isGate) { *(float4*)&Bs[bK][bC*4] = bR; }
        else { Bs[bK*4+0][bC] = bR.x; Bs[bK*4+1][bC] = bR.y;
               Bs[bK*4+2][bC] = bR.z; Bs[bK*4+3][bC] = bR.w; }
        __syncthreads();
        if (kt < 47) {  // prefetch next slab while computing this one
            const int k0 = (kt + 1) * 16;
            aR0 = *(const float4*)(X + (size_t)(m0 + aRow) * 768 + k0 + aKq*4);
            aR1 = *(const float4*)(X + (size_t)(m0 + 64 + aRow) * 768 + k0 + aKq*4);
            if (!isGate) bR = *(const float4*)(Bptr + (size_t)(k0 + bK) * 128 + bC*4);
            else         bR = *(const float4*)(Bptr + k0 + bK*4);
        }
        #pragma unroll 4
        for (int k = 0; k < 16; k++) {
            const float4 a0 = *(const float4*)&As[k][ty*8];
            const float4 a1 = *(const float4*)&As[k][ty*8+4];
            const ulonglong2 bv = *(const ulonglong2*)&Bs[k][tx*4];
            ull q;
            q = pk2(a0.x); acc[0][0]=f2(q,bv.x,acc[0][0]); acc[0][1]=f2(q,bv.y,acc[0][1]);
            q = pk2(a0.y); acc[1][0]=f2(q,bv.x,acc[1][0]); acc[1][1]=f2(q,bv.y,acc[1][1]);
            q = pk2(a0.z); acc[2][0]=f2(q,bv.x,acc[2][0]); acc[2][1]=f2(q,bv.y,acc[2][1]);
            q = pk2(a0.w); acc[3][0]=f2(q,bv.x,acc[3][0]); acc[3][1]=f2(q,bv.y,acc[3][1]);
            q = pk2(a1.x); acc[4][0]=f2(q,bv.x,acc[4][0]); acc[4][1]=f2(q,bv.y,acc[4][1]);
            q = pk2(a1.y); acc[5][0]=f2(q,bv.x,acc[5][0]); acc[5][1]=f2(q,bv.y,acc[5][1]);
            q = pk2(a1.z); acc[6][0]=f2(q,bv.x,acc[6][0]); acc[6][1]=f2(q,bv.y,acc[6][1]);
            q = pk2(a1.w); acc[7][0]=f2(q,bv.x,acc[7][0]); acc[7][1]=f2(q,bv.y,acc[7][1]);
        }
    }

    if (!isGate) {
        const int c = cBase + tx*4;
        #pragma unroll
        for (int i = 0; i < 8; i++) {
            const int row = m0 + ty*8 + i;
            float4 o;
            o.x = lo32(acc[i][0]); o.y = hi32(acc[i][0]);
            o.z = lo32(acc[i][1]); o.w = hi32(acc[i][1]);
            *(float4*)(g_h + (size_t)row * 768 + c) = o;
        }
    } else {
        const int cg = cBase - 768 + tx*4;
        const float4 hb = *(const float4*)(Hb + cg);
        #pragma unroll
        for (int i = 0; i < 8; i++) {
            const int row = m0 + ty*8 + i;
            float4 o;
            o.x = sigm(lo32(acc[i][0]) + hb.x);
            o.y = sigm(hi32(acc[i][0]) + hb.y);
            o.z = sigm(lo32(acc[i][1]) + hb.z);
            o.w = sigm(hi32(acc[i][1]) + hb.w);
            *(float4*)(g_gate + (size_t)row * 768 + cg) = o;
        }
    }
}

// =========================================================================
// Kernel 2: src/dst = <tanh(h[b,h,n,:]), w_src/w_dst>. One warp per row.
// =========================================================================
__global__ __launch_bounds__(256) void srcdst_kernel(
    const float* __restrict__ wsrc, const float* __restrict__ wdst)
{
    const int tid = threadIdx.x, lane = tid & 31, wid = tid >> 5;
    const int gid = blockIdx.x * 8 + wid;          // 0..49151
    const int b = gid / 12288;
    const int r = gid - b * 12288;
    const int h = r >> 11;
    const int n = r & 2047;

    const float4 v  = *(const float4*)(g_h + (size_t)(b*2048 + n)*768 + h*128 + lane*4);
    const float4 ws = *(const float4*)(wsrc + h*128 + lane*4);
    const float4 wd = *(const float4*)(wdst + h*128 + lane*4);
    float t, ss = 0.f, sd = 0.f;
    t = tanhf(v.x); ss += t*ws.x; sd += t*wd.x;
    t = tanhf(v.y); ss += t*ws.y; sd += t*wd.y;
    t = tanhf(v.z); ss += t*ws.z; sd += t*wd.z;
    t = tanhf(v.w); ss += t*ws.w; sd += t*wd.w;
    #pragma unroll
    for (int o = 16; o > 0; o >>= 1) {
        ss += __shfl_xor_sync(0xffffffffu, ss, o);
        sd += __shfl_xor_sync(0xffffffffu, sd, o);
    }
    if (lane == 0) {
        const int idx = (b*6 + h)*2048 + n;
        g_src[idx] = ss; g_dst[idx] = sd;
    }
}

// =========================================================================
// Kernel 3: M[b,h,i] = leaky(src[i] + max_j dst[j]). One block per (b,h).
// leaky is monotone, so this upper-bounds every unmasked score.
// =========================================================================
__global__ __launch_bounds__(256) void rowmax_kernel()
{
    __shared__ float red[256];
    const int bh = blockIdx.x, tid = threadIdx.x;
    float m = -3.0e38f;
    for (int n = tid; n < 2048; n += 256) m = fmaxf(m, g_dst[bh*2048 + n]);
    red[tid] = m; __syncthreads();
    for (int s = 128; s > 0; s >>= 1) {
        if (tid < s) red[tid] = fmaxf(red[tid], red[tid + s]);
        __syncthreads();
    }
    const float mx = red[0];
    for (int n = tid; n < 2048; n += 256) {
        float s = g_src[bh*2048 + n] + mx;
        g_M[bh*2048 + n] = fmaxf(s, 0.2f * s);
    }
}

// =========================================================================
// Kernel 3b: pack adj into transposed bitmask g_adjbits[b][word][n].
// One warp per 32-bit word (ballot over 32 consecutive j).
// =========================================================================
__global__ __launch_bounds__(256) void adjpack_kernel(const int* __restrict__ adj)
{
    const int lane = threadIdx.x & 31, wid = threadIdx.x >> 5;
    const int g = blockIdx.x * 8 + wid;           // word id, 0..524287
    const int b = g >> 17;                         // / (2048*64)
    const int rem = g & 131071;
    const int n = rem >> 6;
    const int w = rem & 63;
    const int v = adj[((size_t)(b*2048) + n)*2048 + w*32 + lane];
    const unsigned m = __ballot_sync(0xffffffffu, v != 0);
    if (lane == 0) g_adjbits[((size_t)b*64 + w)*2048 + n] = m;
}

// =========================================================================
// Kernel 4: fused attention. Block = (64-row i-tile, h, b), 128 threads.
// Per 32-j tile: stage V (warp-per-row, conflict-free) + build masked-exp P
// from the adj bitmask, then register-tiled P@V (8 rows x (4+4 cols), f32x2).
// Epilogue: /l, +bias, ELU, gate residual.
// =========================================================================
__global__ __launch_bounds__(128) void attn_kernel(
    const float* __restrict__ feat_in,
    const float* __restrict__ bias, float* __restrict__ out)
{
    __shared__ __align__(16) float Vs[32][132];
    __shared__ __align__(16) float Ps[32][64];
    __shared__ float sDst[2048];
    __shared__ float sSrc[64];
    __shared__ float sM[64];
    __shared__ float sLinv[64];
    __shared__ float lpart[2][64];

    const int tid = threadIdx.x;
    const int b = blockIdx.z, h = blockIdx.y;
    const int i0 = blockIdx.x * 64;
    const int bh = b*6 + h;
    const int lane = tid & 31, wid = tid >> 5;

    for (int t = tid; t < 2048; t += 128) sDst[t] = g_dst[bh*2048 + t];
    if (tid < 64) {
        sSrc[tid] = g_src[bh*2048 + i0 + tid];
        sM[tid]   = g_M[bh*2048 + i0 + tid];
    }
    __syncthreads();

    const int il = tid & 63, jh = tid >> 6;        // P role: row il, j-half jh
    const float srcv = sSrc[il], Mv = sM[il];
    float psum = 0.f;
    const int ty = tid >> 4, tx = tid & 15;        // GEMM role: 8 rows x (4+4) cols
    const int c0 = tx*4;                           // first col chunk; second = c0+64

    const float* Vg = g_h + (size_t)(b*2048)*768 + h*128;
    const unsigned* abT = g_adjbits + (size_t)b*64*2048 + (i0 + il);  // + jt*2048

    ull acc[8][4];
    #pragma unroll
    for (int i = 0; i < 8; i++)
        #pragma unroll
        for (int q = 0; q < 4; q++) acc[i][q] = 0ull;

    for (int jt = 0; jt < 64; jt++) {
        const int j0 = jt * 32;

        // V tile: warp w stages rows w, w+4, ..., lane covers contiguous 512B row
        #pragma unroll
        for (int r = wid; r < 32; r += 4) {
            float4 v = *(const float4*)(Vg + (size_t)(j0 + r)*768 + lane*4);
            *(float4*)&Vs[r][lane*4] = v;
        }

        // P tile: this thread covers j = j0 + jh*16 + (0..15); mask bits from word jt
        const unsigned am = abT[jt*2048];
        #pragma unroll
        for (int q = 0; q < 4; q++) {
            const int jb = jh*16 + q*4;
            float s, p;
            s = srcv + sDst[j0 + jb + 0]; s = fmaxf(s, 0.2f*s);
            p = ((am >> (jb+0)) & 1u) ? __expf(s - Mv) : 0.f; psum += p; Ps[jb + 0][il] = p;
            s = srcv + sDst[j0 + jb + 1]; s = fmaxf(s, 0.2f*s);
            p = ((am >> (jb+1)) & 1u) ? __expf(s - Mv) : 0.f; psum += p; Ps[jb + 1][il] = p;
            s = srcv + sDst[j0 + jb + 2]; s = fmaxf(s, 0.2f*s);
            p = ((am >> (jb+2)) & 1u) ? __expf(s - Mv) : 0.f; psum += p; Ps[jb + 2][il] = p;
            s = srcv + sDst[j0 + jb + 3]; s = fmaxf(s, 0.2f*s);
            p = ((am >> (jb+3)) & 1u) ? __expf(s - Mv) : 0.f; psum += p; Ps[jb + 3][il] = p;
        }
        __syncthreads();

        // register-tiled P@V (conflict-free: contiguous 16B per lane, bcast dedup)
        #pragma unroll 4
        for (int j = 0; j < 32; j++) {
            const float4 p0 = *(const float4*)&Ps[j][ty*8];
            const float4 p1 = *(const float4*)&Ps[j][ty*8 + 4];
            const ulonglong2 vA = *(const ulonglong2*)&Vs[j][c0];
            const ulonglong2 vB = *(const ulonglong2*)&Vs[j][64 + c0];
            ull q;
            q = pk2(p0.x); acc[0][0]=f2(q,vA.x,acc[0][0]); acc[0][1]=f2(q,vA.y,acc[0][1]);
                           acc[0][2]=f2(q,vB.x,acc[0][2]); acc[0][3]=f2(q,vB.y,acc[0][3]);
            q = pk2(p0.y); acc[1][0]=f2(q,vA.x,acc[1][0]); acc[1][1]=f2(q,vA.y,acc[1][1]);
                           acc[1][2]=f2(q,vB.x,acc[1][2]); acc[1][3]=f2(q,vB.y,acc[1][3]);
            q = pk2(p0.z); acc[2][0]=f2(q,vA.x,acc[2][0]); acc[2][1]=f2(q,vA.y,acc[2][1]);
                           acc[2][2]=f2(q,vB.x,acc[2][2]); acc[2][3]=f2(q,vB.y,acc[2][3]);
            q = pk2(p0.w); acc[3][0]=f2(q,vA.x,acc[3][0]); acc[3][1]=f2(q,vA.y,acc[3][1]);
                           acc[3][2]=f2(q,vB.x,acc[3][2]); acc[3][3]=f2(q,vB.y,acc[3][3]);
            q = pk2(p1.x); acc[4][0]=f2(q,vA.x,acc[4][0]); acc[4][1]=f2(q,vA.y,acc[4][1]);
                           acc[4][2]=f2(q,vB.x,acc[4][2]); acc[4][3]=f2(q,vB.y,acc[4][3]);
            q = pk2(p1.y); acc[5][0]=f2(q,vA.x,acc[5][0]); acc[5][1]=f2(q,vA.y,acc[5][1]);
                           acc[5][2]=f2(q,vB.x,acc[5][2]); acc[5][3]=f2(q,vB.y,acc[5][3]);
            q = pk2(p1.z); acc[6][0]=f2(q,vA.x,acc[6][0]); acc[6][1]=f2(q,vA.y,acc[6][1]);
                           acc[6][2]=f2(q,vB.x,acc[6][2]); acc[6][3]=f2(q,vB.y,acc[6][3]);
            q = pk2(p1.w); acc[7][0]=f2(q,vA.x,acc[7][0]); acc[7][1]=f2(q,vA.y,acc[7][1]);
                           acc[7][2]=f2(q,vB.x,acc[7][2]); acc[7][3]=f2(q,vB.y,acc[7][3]);
        }
        __syncthreads();
    }

    // softmax denominators
    lpart[jh][il] = psum;
    __syncthreads();
    if (tid < 64) sLinv[tid] = 1.0f / (lpart[0][tid] + lpart[1][tid]);
    __syncthreads();

    // epilogue: /l + bias, ELU, gated residual with feat_in
    const float4 bv0 = *(const float4*)(bias + c0);
    const float4 bv1 = *(const float4*)(bias + 64 + c0);
    #pragma unroll
    for (int i = 0; i < 8; i++) {
        const int row = ty*8 + i;
        const int n = i0 + row;
        const float linv = sLinv[row];
        const size_t base = ((size_t)(b*2048) + n)*768 + h*128 + c0;
        const float4 x0 = *(const float4*)(feat_in + base);
        const float4 x1 = *(const float4*)(feat_in + base + 64);
        const float4 g0 = *(const float4*)(g_gate + base);
        const float4 g1 = *(const float4*)(g_gate + base + 64);
        float fo, e;
        float4 o0, o1;
        fo = lo32(acc[i][0])*linv + bv0.x; e = (fo > 0.f) ? fo : expm1f(fo); o0.x = x0.x + g0.x*(e - x0.x);
        fo = hi32(acc[i][0])*linv + bv0.y; e = (fo > 0.f) ? fo : expm1f(fo); o0.y = x0.y + g0.y*(e - x0.y);
        fo = lo32(acc[i][1])*linv + bv0.z; e = (fo > 0.f) ? fo : expm1f(fo); o0.z = x0.z + g0.z*(e - x0.z);
        fo = hi32(acc[i][1])*linv + bv0.w; e = (fo > 0.f) ? fo : expm1f(fo); o0.w = x0.w + g0.w*(e - x0.w);
        fo = lo32(acc[i][2])*linv + bv1.x; e = (fo > 0.f) ? fo : expm1f(fo); o1.x = x1.x + g1.x*(e - x1.x);
        fo = hi32(acc[i][2])*linv + bv1.y; e = (fo > 0.f) ? fo : expm1f(fo); o1.y = x1.y + g1.y*(e - x1.y);
        fo = lo32(acc[i][3])*linv + bv1.z; e = (fo > 0.f) ? fo : expm1f(fo); o1.z = x1.z + g1.z*(e - x1.z);
        fo = hi32(acc[i][3])*linv + bv1.w; e = (fo > 0.f) ? fo : expm1f(fo); o1.w = x1.w + g1.w*(e - x1.w);
        *(float4*)(out + base)      = o0;
        *(float4*)(out + base + 64) = o1;
    }
}

extern "C" void kernel_launch(void* const* d_in, const int* in_sizes, int n_in,
                              void* d_out, int out_size) {
    (void)in_sizes; (void)n_in; (void)out_size;
    const float* feat_in = (const float*)d_in[0];
    const int*   adj     = (const int*)d_in[1];
    const float* W       = (const float*)d_in[2];
    const float* bvec    = (const float*)d_in[3];
    const float* w_src   = (const float*)d_in[4];
    const float* w_dst   = (const float*)d_in[5];
    const float* H_w     = (const float*)d_in[6];
    const float* H_b     = (const float*)d_in[7];
    float* out = (float*)d_out;

    proj_gemm<<<dim3(24, 64), 256>>>(feat_in, W, H_w, H_b);
    adjpack_kernel<<<65536, 256>>>(adj);
    srcdst_kernel<<<6144, 256>>>(w_src, w_dst);
    rowmax_kernel<<<24, 256>>>();
    attn_kernel<<<dim3(32, 6, 4), 128>>>(feat_in, bvec, out);
}

// round 11
// speedup vs baseline: 1.2405x; 1.0146x over previous
#include <cuda_runtime.h>
#include <cuda_bf16.h>
#include <math.h>

typedef unsigned long long ull;

#define Bb 4
#define Nn 2048
#define Dd 768
#define Hh 6
#define Do_ 128

__device__ __align__(16) float g_h[Bb*Nn*Dd];     // per-head projected features, col = h*128+o
__device__ __align__(16) float g_gate[Bb*Nn*Dd];  // sigmoid gate
__device__ float g_src[Bb*Hh*Nn];
__device__ float g_dst[Bb*Hh*Nn];
__device__ float g_M[Bb*Hh*Nn];                   // leaky(src_i + max_j dst_j)
__device__ unsigned g_adjbits[Bb*64*Nn];          // transposed bitmask: [b][word(j/32)][n]

// ---------- packed f32x2 helpers ----------
__device__ __forceinline__ ull pk2(float x) {
    ull r; asm("mov.b64 %0, {%1, %2};" : "=l"(r) : "f"(x), "f"(x)); return r;
}
__device__ __forceinline__ ull f2(ull a, ull b, ull c) {
    ull d; asm("fma.rn.f32x2 %0, %1, %2, %3;" : "=l"(d) : "l"(a), "l"(b), "l"(c)); return d;
}
__device__ __forceinline__ float lo32(ull v) { return __uint_as_float((unsigned)(v & 0xffffffffull)); }
__device__ __forceinline__ float hi32(ull v) { return __uint_as_float((unsigned)(v >> 32)); }
__device__ __forceinline__ float sigm(float x) { return 1.0f / (1.0f + __expf(-x)); }

#define CP_ASYNC16(dst_u32, src_ptr) \
    asm volatile("cp.async.cg.shared.global [%0], [%1], 16;" :: "r"(dst_u32), "l"(src_ptr))
#define CP_COMMIT()  asm volatile("cp.async.commit_group;" ::: "memory")
#define CP_WAIT0()   asm volatile("cp.async.wait_group 0;" ::: "memory")

// =========================================================================
// Kernel 1: dual GEMM. A = X [8192 x 768]. Global cols 0..767 -> h (B from W),
// cols 768..1535 -> gate (B = H_w rows, NT access). BM=128 BN=64 BK=16,
// 256 threads, thread tile 8 rows x 4 cols (2 f32x2 pairs).
// =========================================================================
__global__ __launch_bounds__(256) void proj_gemm(
    const float* __restrict__ X, const float* __restrict__ W,
    const float* __restrict__ Hw, const float* __restrict__ Hb)
{
    __shared__ __align__(16) float As[16][128];
    __shared__ __align__(16) float Bs[16][64];

    const int tid   = threadIdx.x;
    const int cBase = blockIdx.x * 64;        // 0..1472
    const bool isGate = (cBase >= 768);
    const int m0    = blockIdx.y * 128;

    const int aRow = tid >> 2;                // 0..63
    const int aKq  = tid & 3;                 // k-quad

    int bK, bC;
    const float* Bptr;
    if (!isGate) {
        bK = tid >> 4; bC = tid & 15;
        Bptr = W + (size_t)(cBase >> 7) * (768*128) + (cBase & 127);
    } else {
        bC = tid >> 2; bK = tid & 3;
        Bptr = Hw + (size_t)(cBase - 768 + bC) * 768;
    }

    float4 aR0, aR1, bR;
    aR0 = *(const float4*)(X + (size_t)(m0 + aRow) * 768 + aKq*4);
    aR1 = *(const float4*)(X + (size_t)(m0 + 64 + aRow) * 768 + aKq*4);
    if (!isGate) bR = *(const float4*)(Bptr + (size_t)bK * 128 + bC*4);
    else         bR = *(const float4*)(Bptr + bK*4);

    const int ty = tid >> 4, tx = tid & 15;
    ull acc[8][2];
    #pragma unroll
    for (int i = 0; i < 8; i++) { acc[i][0] = 0ull; acc[i][1] = 0ull; }

    for (int kt = 0; kt < 48; kt++) {
        __syncthreads();
        As[aKq*4+0][aRow] = aR0.x; As[aKq*4+1][aRow] = aR0.y;
        As[aKq*4+2][aRow] = aR0.z; As[aKq*4+3][aRow] = aR0.w;
        As[aKq*4+0][64+aRow] = aR1.x; As[aKq*4+1][64+aRow] = aR1.y;
        As[aKq*4+2][64+aRow] = aR1.z; As[aKq*4+3][64+aRow] = aR1.w;
        if (!isGate) { *(float4*)&Bs[bK][bC*4] = bR; }
        else { Bs[bK*4+0][bC] = bR.x; Bs[bK*4+1][bC] = bR.y;
               Bs[bK*4+2][bC] = bR.z; Bs[bK*4+3][bC] = bR.w; }
        __syncthreads();
        if (kt < 47) {  // prefetch next slab while computing this one
            const int k0 = (kt + 1) * 16;
            aR0 = *(const float4*)(X + (size_t)(m0 + aRow) * 768 + k0 + aKq*4);
            aR1 = *(const float4*)(X + (size_t)(m0 + 64 + aRow) * 768 + k0 + aKq*4);
            if (!isGate) bR = *(const float4*)(Bptr + (size_t)(k0 + bK) * 128 + bC*4);
            else         bR = *(const float4*)(Bptr + k0 + bK*4);
        }
        #pragma unroll 4
        for (int k = 0; k < 16; k++) {
            const float4 a0 = *(const float4*)&As[k][ty*8];
            const float4 a1 = *(const float4*)&As[k][ty*8+4];
            const ulonglong2 bv = *(const ulonglong2*)&Bs[k][tx*4];
            ull q;
            q = pk2(a0.x); acc[0][0]=f2(q,bv.x,acc[0][0]); acc[0][1]=f2(q,bv.y,acc[0][1]);
            q = pk2(a0.y); acc[1][0]=f2(q,bv.x,acc[1][0]); acc[1][1]=f2(q,bv.y,acc[1][1]);
            q = pk2(a0.z); acc[2][0]=f2(q,bv.x,acc[2][0]); acc[2][1]=f2(q,bv.y,acc[2][1]);
            q = pk2(a0.w); acc[3][0]=f2(q,bv.x,acc[3][0]); acc[3][1]=f2(q,bv.y,acc[3][1]);
            q = pk2(a1.x); acc[4][0]=f2(q,bv.x,acc[4][0]); acc[4][1]=f2(q,bv.y,acc[4][1]);
            q = pk2(a1.y); acc[5][0]=f2(q,bv.x,acc[5][0]); acc[5][1]=f2(q,bv.y,acc[5][1]);
            q = pk2(a1.z); acc[6][0]=f2(q,bv.x,acc[6][0]); acc[6][1]=f2(q,bv.y,acc[6][1]);
            q = pk2(a1.w); acc[7][0]=f2(q,bv.x,acc[7][0]); acc[7][1]=f2(q,bv.y,acc[7][1]);
        }
    }

    if (!isGate) {
        const int c = cBase + tx*4;
        #pragma unroll
        for (int i = 0; i < 8; i++) {
            const int row = m0 + ty*8 + i;
            float4 o;
            o.x = lo32(acc[i][0]); o.y = hi32(acc[i][0]);
            o.z = lo32(acc[i][1]); o.w = hi32(acc[i][1]);
            *(float4*)(g_h + (size_t)row * 768 + c) = o;
        }
    } else {
        const int cg = cBase - 768 + tx*4;
        const float4 hb = *(const float4*)(Hb + cg);
        #pragma unroll
        for (int i = 0; i < 8; i++) {
            const int row = m0 + ty*8 + i;
            float4 o;
            o.x = sigm(lo32(acc[i][0]) + hb.x);
            o.y = sigm(hi32(acc[i][0]) + hb.y);
            o.z = sigm(lo32(acc[i][1]) + hb.z);
            o.w = sigm(hi32(acc[i][1]) + hb.w);
            *(float4*)(g_gate + (size_t)row * 768 + cg) = o;
        }
    }
}

// =========================================================================
// Kernel 2: src/dst = <tanh(h[b,h,n,:]), w_src/w_dst>. One warp per row.
// =========================================================================
__global__ __launch_bounds__(256) void srcdst_kernel(
    const float* __restrict__ wsrc, const float* __restrict__ wdst)
{
    const int tid = threadIdx.x, lane = tid & 31, wid = tid >> 5;
    const int gid = blockIdx.x * 8 + wid;          // 0..49151
    const int b = gid / 12288;
    const int r = gid - b * 12288;
    const int h = r >> 11;
    const int n = r & 2047;

    const float4 v  = *(const float4*)(g_h + (size_t)(b*2048 + n)*768 + h*128 + lane*4);
    const float4 ws = *(const float4*)(wsrc + h*128 + lane*4);
    const float4 wd = *(const float4*)(wdst + h*128 + lane*4);
    float t, ss = 0.f, sd = 0.f;
    t = tanhf(v.x); ss += t*ws.x; sd += t*wd.x;
    t = tanhf(v.y); ss += t*ws.y; sd += t*wd.y;
    t = tanhf(v.z); ss += t*ws.z; sd += t*wd.z;
    t = tanhf(v.w); ss += t*ws.w; sd += t*wd.w;
    #pragma unroll
    for (int o = 16; o > 0; o >>= 1) {
        ss += __shfl_xor_sync(0xffffffffu, ss, o);
        sd += __shfl_xor_sync(0xffffffffu, sd, o);
    }
    if (lane == 0) {
        const int idx = (b*6 + h)*2048 + n;
        g_src[idx] = ss; g_dst[idx] = sd;
    }
}

// =========================================================================
// Kernel 3: M[b,h,i] = leaky(src[i] + max_j dst[j]). One block per (b,h).
// leaky is monotone, so this upper-bounds every unmasked score.
// =========================================================================
__global__ __launch_bounds__(256) void rowmax_kernel()
{
    __shared__ float red[256];
    const int bh = blockIdx.x, tid = threadIdx.x;
    float m = -3.0e38f;
    for (int n = tid; n < 2048; n += 256) m = fmaxf(m, g_dst[bh*2048 + n]);
    red[tid] = m; __syncthreads();
    for (int s = 128; s > 0; s >>= 1) {
        if (tid < s) red[tid] = fmaxf(red[tid], red[tid + s]);
        __syncthreads();
    }
    const float mx = red[0];
    for (int n = tid; n < 2048; n += 256) {
        float s = g_src[bh*2048 + n] + mx;
        g_M[bh*2048 + n] = fmaxf(s, 0.2f * s);
    }
}

// =========================================================================
// Kernel 3b: pack adj into transposed bitmask g_adjbits[b][word][n].
// One warp per 32-bit word (ballot over 32 consecutive j).
// =========================================================================
__global__ __launch_bounds__(256) void adjpack_kernel(const int* __restrict__ adj)
{
    const int lane = threadIdx.x & 31, wid = threadIdx.x >> 5;
    const int g = blockIdx.x * 8 + wid;           // word id, 0..524287
    const int b = g >> 17;                         // / (2048*64)
    const int rem = g & 131071;
    const int n = rem >> 6;
    const int w = rem & 63;
    const int v = adj[((size_t)(b*2048) + n)*2048 + w*32 + lane];
    const unsigned m = __ballot_sync(0xffffffffu, v != 0);
    if (lane == 0) g_adjbits[((size_t)b*64 + w)*2048 + n] = m;
}

// =========================================================================
// Kernel 4: fused attention, software-pipelined. Block = (64 i-rows, h, b),
// 128 threads. Double-buffered Vs (cp.async GMEM->SMEM) and Ps; one barrier
// per 32-j tile. While GEMMing tile jt, the same warps cp.async V[jt+1] and
// exp-build P[jt+1] into the idle buffers. Epilogue: /l, +bias, ELU, gate.
// Dynamic smem layout (floats):
//   Vs [2][32][128] @ 0       (8192)
//   Ps [2][32][64]  @ 8192    (4096)
//   sDst[2048]      @ 12288
//   sSrc[64] sM[64] sLinv[64] lpart[2][64] @ 14336
// total 14656 floats = 58624 B
// =========================================================================
#define ATTN_SMEM_BYTES 58624

__global__ __launch_bounds__(128) void attn_kernel(
    const float* __restrict__ feat_in,
    const float* __restrict__ bias, float* __restrict__ out)
{
    extern __shared__ __align__(16) float smem[];
    float* Vsm   = smem;            // [2][32][128]
    float* Psm   = smem + 8192;     // [2][32][64]
    float* sDst  = smem + 12288;
    float* sSrc  = smem + 14336;
    float* sM    = sSrc + 64;
    float* sLinv = sM + 64;
    float* lpart = sLinv + 64;      // [2][64]

    const int tid = threadIdx.x;
    const int b = blockIdx.z, h = blockIdx.y;
    const int i0 = blockIdx.x * 64;
    const int bh = b*6 + h;
    const int lane = tid & 31, wid = tid >> 5;

    for (int t = tid; t < 2048; t += 128) sDst[t] = g_dst[bh*2048 + t];
    if (tid < 64) {
        sSrc[tid] = g_src[bh*2048 + i0 + tid];
        sM[tid]   = g_M[bh*2048 + i0 + tid];
    }
    __syncthreads();

    const int il = tid & 63, jh = tid >> 6;        // P role: row il, j-half jh
    const float srcv = sSrc[il], Mv = sM[il];
    float psum = 0.f;
    const int ty = tid >> 4, tx = tid & 15;        // GEMM role: 8 rows x (4+4) cols
    const int c0 = tx*4;

    const float* Vg = g_h + (size_t)(b*2048)*768 + h*128;
    const unsigned* abT = g_adjbits + (size_t)b*64*2048 + (i0 + il);

    const unsigned vsBase = (unsigned)__cvta_generic_to_shared(Vsm);
    // this warp's V rows: wid + 4r (r=0..7); lane covers 16B of the 512B row
    const unsigned vDstBase = vsBase + (unsigned)(wid*512 + lane*16);
    const float* vSrcBase = Vg + (size_t)wid*768 + lane*4;

    ull acc[8][4];
    #pragma unroll
    for (int i = 0; i < 8; i++)
        #pragma unroll
        for (int q = 0; q < 4; q++) acc[i][q] = 0ull;

    // ---- stage V tile jt into buffer buf (cp.async, no regs held) ----
    auto stageV = [&](int jt, int buf) {
        const float* src = vSrcBase + (size_t)jt*32*768;
        const unsigned dst = vDstBase + (unsigned)buf*16384u;
        #pragma unroll
        for (int r = 0; r < 8; r++)
            CP_ASYNC16(dst + (unsigned)r*2048u, src + (size_t)r*4*768);
        CP_COMMIT();
    };
    // ---- build P tile jt into buffer buf ----
    auto buildP = [&](int jt, int buf) {
        const int j0 = jt * 32;
        const unsigned am = abT[jt*2048];
        float* Pb = Psm + buf*2048;
        #pragma unroll
        for (int q = 0; q < 4; q++) {
            const int jb = jh*16 + q*4;
            float s, p;
            s = srcv + sDst[j0 + jb + 0]; s = fmaxf(s, 0.2f*s);
            p = ((am >> (jb+0)) & 1u) ? __expf(s - Mv) : 0.f; psum += p; Pb[(jb+0)*64 + il] = p;
            s = srcv + sDst[j0 + jb + 1]; s = fmaxf(s, 0.2f*s);
            p = ((am >> (jb+1)) & 1u) ? __expf(s - Mv) : 0.f; psum += p; Pb[(jb+1)*64 + il] = p;
            s = srcv + sDst[j0 + jb + 2]; s = fmaxf(s, 0.2f*s);
            p = ((am >> (jb+2)) & 1u) ? __expf(s - Mv) : 0.f; psum += p; Pb[(jb+2)*64 + il] = p;
            s = srcv + sDst[j0 + jb + 3]; s = fmaxf(s, 0.2f*s);
            p = ((am >> (jb+3)) & 1u) ? __expf(s - Mv) : 0.f; psum += p; Pb[(jb+3)*64 + il] = p;
        }
    };

    // prolog: tile 0 into buffer 0
    stageV(0, 0);
    buildP(0, 0);
    CP_WAIT0();
    __syncthreads();

    for (int jt = 0; jt < 64; jt++) {
        const int cur = jt & 1;

        if (jt < 63) {
            stageV(jt + 1, cur ^ 1);   // background copy during GEMM
            buildP(jt + 1, cur ^ 1);   // exp overlaps other warps' GEMM
        }

        // register-tiled P@V on buffer cur
        const float* Pc = Psm + cur*2048;
        const float* Vc = Vsm + cur*4096;
        #pragma unroll 4
        for (int j = 0; j < 32; j++) {
            const float4 p0 = *(const float4*)&Pc[j*64 + ty*8];
            const float4 p1 = *(const float4*)&Pc[j*64 + ty*8 + 4];
            const ulonglong2 vA = *(const ulonglong2*)&Vc[j*128 + c0];
            const ulonglong2 vB = *(const ulonglong2*)&Vc[j*128 + 64 + c0];
            ull q;
            q = pk2(p0.x); acc[0][0]=f2(q,vA.x,acc[0][0]); acc[0][1]=f2(q,vA.y,acc[0][1]);
                           acc[0][2]=f2(q,vB.x,acc[0][2]); acc[0][3]=f2(q,vB.y,acc[0][3]);
            q = pk2(p0.y); acc[1][0]=f2(q,vA.x,acc[1][0]); acc[1][1]=f2(q,vA.y,acc[1][1]);
                           acc[1][2]=f2(q,vB.x,acc[1][2]); acc[1][3]=f2(q,vB.y,acc[1][3]);
            q = pk2(p0.z); acc[2][0]=f2(q,vA.x,acc[2][0]); acc[2][1]=f2(q,vA.y,acc[2][1]);
                           acc[2][2]=f2(q,vB.x,acc[2][2]); acc[2][3]=f2(q,vB.y,acc[2][3]);
            q = pk2(p0.w); acc[3][0]=f2(q,vA.x,acc[3][0]); acc[3][1]=f2(q,vA.y,acc[3][1]);
                           acc[3][2]=f2(q,vB.x,acc[3][2]); acc[3][3]=f2(q,vB.y,acc[3][3]);
            q = pk2(p1.x); acc[4][0]=f2(q,vA.x,acc[4][0]); acc[4][1]=f2(q,vA.y,acc[4][1]);
                           acc[4][2]=f2(q,vB.x,acc[4][2]); acc[4][3]=f2(q,vB.y,acc[4][3]);
            q = pk2(p1.y); acc[5][0]=f2(q,vA.x,acc[5][0]); acc[5][1]=f2(q,vA.y,acc[5][1]);
                           acc[5][2]=f2(q,vB.x,acc[5][2]); acc[5][3]=f2(q,vB.y,acc[5][3]);
            q = pk2(p1.z); acc[6][0]=f2(q,vA.x,acc[6][0]); acc[6][1]=f2(q,vA.y,acc[6][1]);
                           acc[6][2]=f2(q,vB.x,acc[6][2]); acc[6][3]=f2(q,vB.y,acc[6][3]);
            q = pk2(p1.w); acc[7][0]=f2(q,vA.x,acc[7][0]); acc[7][1]=f2(q,vA.y,acc[7][1]);
                           acc[7][2]=f2(q,vB.x,acc[7][2]); acc[7][3]=f2(q,vB.y,acc[7][3]);
        }

        if (jt < 63) CP_WAIT0();   // V[jt+1] landed (issued before GEMM)
        __syncthreads();           // publish Ps/Vs buffers for next tile
    }

    // softmax denominators
    lpart[jh*64 + il] = psum;
    __syncthreads();
    if (tid < 64) sLinv[tid] = 1.0f / (lpart[tid] + lpart[64 + tid]);
    __syncthreads();

    // epilogue: /l + bias, ELU, gated residual with feat_in
    const float4 bv0 = *(const float4*)(bias + c0);
    const float4 bv1 = *(const float4*)(bias + 64 + c0);
    #pragma unroll
    for (int i = 0; i < 8; i++) {
        const int row = ty*8 + i;
        const int n = i0 + row;
        const float linv = sLinv[row];
        const size_t base = ((size_t)(b*2048) + n)*768 + h*128 + c0;
        const float4 x0 = *(const float4*)(feat_in + base);
        const float4 x1 = *(const float4*)(feat_in + base + 64);
        const float4 g0 = *(const float4*)(g_gate + base);
        const float4 g1 = *(const float4*)(g_gate + base + 64);
        float fo, e;
        float4 o0, o1;
        fo = lo32(acc[i][0])*linv + bv0.x; e = (fo > 0.f) ? fo : expm1f(fo); o0.x = x0.x + g0.x*(e - x0.x);
        fo = hi32(acc[i][0])*linv + bv0.y; e = (fo > 0.f) ? fo : expm1f(fo); o0.y = x0.y + g0.y*(e - x0.y);
        fo = lo32(acc[i][1])*linv + bv0.z; e = (fo > 0.f) ? fo : expm1f(fo); o0.z = x0.z + g0.z*(e - x0.z);
        fo = hi32(acc[i][1])*linv + bv0.w; e = (fo > 0.f) ? fo : expm1f(fo); o0.w = x0.w + g0.w*(e - x0.w);
        fo = lo32(acc[i][2])*linv + bv1.x; e = (fo > 0.f) ? fo : expm1f(fo); o1.x = x1.x + g1.x*(e - x1.x);
        fo = hi32(acc[i][2])*linv + bv1.y; e = (fo > 0.f) ? fo : expm1f(fo); o1.y = x1.y + g1.y*(e - x1.y);
        fo = lo32(acc[i][3])*linv + bv1.z; e = (fo > 0.f) ? fo : expm1f(fo); o1.z = x1.z + g1.z*(e - x1.z);
        fo = hi32(acc[i][3])*linv + bv1.w; e = (fo > 0.f) ? fo : expm1f(fo); o1.w = x1.w + g1.w*(e - x1.w);
        *(float4*)(out + base)      = o0;
        *(float4*)(out + base + 64) = o1;
    }
}

extern "C" void kernel_launch(void* const* d_in, const int* in_sizes, int n_in,
                              void* d_out, int out_size) {
    (void)in_sizes; (void)n_in; (void)out_size;
    const float* feat_in = (const float*)d_in[0];
    const int*   adj     = (const int*)d_in[1];
    const float* W       = (const float*)d_in[2];
    const float* bvec    = (const float*)d_in[3];
    const float* w_src   = (const float*)d_in[4];
    const float* w_dst   = (const float*)d_in[5];
    const float* H_w     = (const float*)d_in[6];
    const float* H_b     = (const float*)d_in[7];
    float* out = (float*)d_out;

    cudaFuncSetAttribute(attn_kernel,
                         cudaFuncAttributeMaxDynamicSharedMemorySize, ATTN_SMEM_BYTES);

    proj_gemm<<<dim3(24, 64), 256>>>(feat_in, W, H_w, H_b);
    adjpack_kernel<<<65536, 256>>>(adj);
    srcdst_kernel<<<6144, 256>>>(w_src, w_dst);
    rowmax_kernel<<<24, 256>>>();
    attn_kernel<<<dim3(32, 6, 4), 128, ATTN_SMEM_BYTES>>>(feat_in, bvec, out);
}

// round 13
// speedup vs baseline: 1.6133x; 1.3005x over previous
#include <cuda_runtime.h>
#include <cuda_bf16.h>
#include <math.h>

typedef unsigned long long ull;

#define Bb 4
#define Nn 2048
#define Dd 768
#define Hh 6
#define Do_ 128

__device__ __align__(16) float g_h[Bb*Nn*Dd];     // per-head projected features, col = h*128+o
__device__ __align__(16) float g_gate[Bb*Nn*Dd];  // sigmoid gate
__device__ float g_src[Bb*Hh*Nn];
__device__ float g_dst[Bb*Hh*Nn];
__device__ float g_M[Bb*Hh*Nn];                   // leaky(src_i + max_j dst_j)
__device__ unsigned g_adjbits[Bb*64*Nn];          // transposed bitmask: [b][word(j/32)][n]

// bf16 split operands for the MMA projection GEMM
__device__ __align__(16) __nv_bfloat16 g_Xhi[Bb*Nn*Dd];
__device__ __align__(16) __nv_bfloat16 g_Xlo[Bb*Nn*Dd];
__device__ __align__(16) __nv_bfloat16 g_Bhi[1536*Dd];   // B[c][i]: c<768 -> W[h][i][o], else H_w row
__device__ __align__(16) __nv_bfloat16 g_Blo[1536*Dd];

// ---------- packed f32x2 helpers ----------
__device__ __forceinline__ ull pk2(float x) {
    ull r; asm("mov.b64 %0, {%1, %2};" : "=l"(r) : "f"(x), "f"(x)); return r;
}
__device__ __forceinline__ ull f2(ull a, ull b, ull c) {
    ull d; asm("fma.rn.f32x2 %0, %1, %2, %3;" : "=l"(d) : "l"(a), "l"(b), "l"(c)); return d;
}
__device__ __forceinline__ float lo32(ull v) { return __uint_as_float((unsigned)(v & 0xffffffffull)); }
__device__ __forceinline__ float hi32(ull v) { return __uint_as_float((unsigned)(v >> 32)); }
__device__ __forceinline__ float sigm(float x) { return 1.0f / (1.0f + __expf(-x)); }

#define CP_ASYNC16(dst_u32, src_ptr) \
    asm volatile("cp.async.cg.shared.global [%0], [%1], 16;" :: "r"(dst_u32), "l"(src_ptr))
#define CP_COMMIT()  asm volatile("cp.async.commit_group;" ::: "memory")
#define CP_WAIT0()   asm volatile("cp.async.wait_group 0;" ::: "memory")
#define CP_WAIT1()   asm volatile("cp.async.wait_group 1;" ::: "memory")

__device__ __forceinline__ unsigned smem_u32(const void* p) {
    return (unsigned)__cvta_generic_to_shared(p);
}

#define LDMX4(r0, r1, r2, r3, addr) \
    asm volatile("ldmatrix.sync.aligned.m8n8.x4.shared.b16 {%0,%1,%2,%3}, [%4];" \
        : "=r"(r0), "=r"(r1), "=r"(r2), "=r"(r3) : "r"(addr))

#define MMA16816(d, a0, a1, a2, a3, b0, b1) \
    asm volatile("mma.sync.aligned.m16n8k16.row.col.f32.bf16.bf16.f32 " \
        "{%0,%1,%2,%3}, {%4,%5,%6,%7}, {%8,%9}, {%0,%1,%2,%3};" \
        : "+f"((d)[0]), "+f"((d)[1]), "+f"((d)[2]), "+f"((d)[3]) \
        : "r"(a0), "r"(a1), "r"(a2), "r"(a3), "r"(b0), "r"(b1))

// =========================================================================
// Prep 1: split X into hi/lo bf16. 4 floats per thread.
// =========================================================================
__global__ __launch_bounds__(256) void splitX_kernel(const float* __restrict__ X)
{
    const int t = blockIdx.x * 256 + threadIdx.x;       // 0..1572863
    const float4 v = ((const float4*)X)[t];
    __nv_bfloat16 h0 = __float2bfloat16(v.x), h1 = __float2bfloat16(v.y);
    __nv_bfloat16 h2 = __float2bfloat16(v.z), h3 = __float2bfloat16(v.w);
    __nv_bfloat16 l0 = __float2bfloat16(v.x - __bfloat162float(h0));
    __nv_bfloat16 l1 = __float2bfloat16(v.y - __bfloat162float(h1));
    __nv_bfloat16 l2 = __float2bfloat16(v.z - __bfloat162float(h2));
    __nv_bfloat16 l3 = __float2bfloat16(v.w - __bfloat162float(h3));
    __nv_bfloat162* Hi = (__nv_bfloat162*)g_Xhi;
    __nv_bfloat162* Lo = (__nv_bfloat162*)g_Xlo;
    Hi[t*2]   = __nv_bfloat162(h0, h1);  Hi[t*2+1] = __nv_bfloat162(h2, h3);
    Lo[t*2]   = __nv_bfloat162(l0, l1);  Lo[t*2+1] = __nv_bfloat162(l2, l3);
}

// =========================================================================
// Prep 2: build concatenated B [1536 x 768] K-major, split hi/lo.
// c<768: B[c][i] = W[h=c>>7][i][o=c&127]; c>=768: B[c][i] = H_w[c-768][i].
// =========================================================================
__global__ __launch_bounds__(256) void buildB_kernel(
    const float* __restrict__ W, const float* __restrict__ Hw)
{
    const int t = blockIdx.x * 256 + threadIdx.x;       // 0..1179647
    const int c = t / 768, i = t - c * 768;
    float v;
    if (c < 768) v = W[(((size_t)(c >> 7) * 768 + i) * 128) + (c & 127)];
    else         v = Hw[(size_t)(c - 768) * 768 + i];
    const __nv_bfloat16 hi = __float2bfloat16(v);
    g_Bhi[t] = hi;
    g_Blo[t] = __float2bfloat16(v - __bfloat162float(hi));
}

// =========================================================================
// Kernel 1: bf16 3-term split GEMM via ldmatrix + mma.sync (base-target HMMA).
// C[8192,1536] = X*B^T; BM=128 BN=128 BK=32, 256 thr, warp tile 32x64.
// Smem rows padded to 80B (16B-bank stride 5 mod 8 -> ldmatrix conflict-free).
// Double-buffered cp.async; accums in registers (no mbarriers).
// Stage layout: [Ahi|Alo|Bhi|Blo] x 128 rows x 80B = 40960B; 2 stages.
// =========================================================================
#define PROJ_SMEM_BYTES (81920 + 1024)

__global__ __launch_bounds__(256, 2) void proj_mma(const float* __restrict__ Hb)
{
    extern __shared__ __align__(16) char dynsm[];

    const int tid  = threadIdx.x;
    const int wid  = tid >> 5, lane = tid & 31;
    const int cBase = blockIdx.x * 128;     // 0..1408
    const int m0    = blockIdx.y * 128;

    const unsigned dynBase = (smem_u32(dynsm) + 1023u) & ~1023u;

    const int warpM = (wid & 3) * 32;       // 4 warps over M
    const int warpN = (wid >> 2) * 64;      // 2 warps over N

    const __nv_bfloat16* baseSrc[4] = {
        g_Xhi + (size_t)m0 * 768, g_Xlo + (size_t)m0 * 768,
        g_Bhi + (size_t)cBase * 768, g_Blo + (size_t)cBase * 768 };

    // ---- stage chunk kc (BK=32) into stage s ----
    auto stage = [&](int kc, int s) {
        const unsigned sb = dynBase + (unsigned)s * 40960u;
        #pragma unroll
        for (int rep = 0; rep < 8; rep++) {
            const int u = rep * 256 + tid;          // 0..2047
            const int T = u >> 9;
            const int rc = u & 511;
            const int row = rc >> 2, c16 = rc & 3;
            CP_ASYNC16(sb + (unsigned)(T * 10240 + row * 80 + c16 * 16),
                       (const char*)(baseSrc[T] + (size_t)row * 768 + kc * 32 + c16 * 8));
        }
        CP_COMMIT();
    };

    // per-lane ldmatrix address components
    const int grp = lane >> 3, l7 = lane & 7;
    // A tile (16 rows @R0, k16 @K0): row = R0 + (grp&1)*8 + l7 ; koff16 = (grp>>1)*16B
    const unsigned aLane = (unsigned)(((grp & 1) * 8 + l7) * 80 + (grp >> 1) * 16);
    // B tile (16 n-rows @N0, k16 @K0): n = N0 + (grp>>1)*8 + l7 ; koff = (grp&1)*16B
    const unsigned bLane = (unsigned)(((grp >> 1) * 8 + l7) * 80 + (grp & 1) * 16);

    float acc[2][8][4];
    #pragma unroll
    for (int mi = 0; mi < 2; mi++)
        #pragma unroll
        for (int ni = 0; ni < 8; ni++)
            #pragma unroll
            for (int q = 0; q < 4; q++) acc[mi][ni][q] = 0.f;

    stage(0, 0);
    stage(1, 1);

    for (int kc = 0; kc < 24; kc++) {
        const int s = kc & 1;
        CP_WAIT1();
        __syncthreads();

        const unsigned sb  = dynBase + (unsigned)s * 40960u;
        const unsigned aHiB = sb            + (unsigned)(warpM * 80) + aLane;
        const unsigned aLoB = sb + 10240u   + (unsigned)(warpM * 80) + aLane;
        const unsigned bHiB = sb + 20480u   + (unsigned)(warpN * 80) + bLane;
        const unsigned bLoB = sb + 30720u   + (unsigned)(warpN * 80) + bLane;

        #pragma unroll
        for (int ks = 0; ks < 2; ks++) {
            const unsigned ko = (unsigned)(ks * 32);
            unsigned ah[2][4], al[2][4];
            LDMX4(ah[0][0], ah[0][1], ah[0][2], ah[0][3], aHiB + ko);
            LDMX4(ah[1][0], ah[1][1], ah[1][2], ah[1][3], aHiB + ko + 16u*80u);
            LDMX4(al[0][0], al[0][1], al[0][2], al[0][3], aLoB + ko);
            LDMX4(al[1][0], al[1][1], al[1][2], al[1][3], aLoB + ko + 16u*80u);
            #pragma unroll
            for (int nb = 0; nb < 4; nb++) {      // each x4 covers 2 n8-tiles
                unsigned bh0, bh1, bh2, bh3, bl0, bl1, bl2, bl3;
                LDMX4(bh0, bh1, bh2, bh3, bHiB + ko + (unsigned)(nb * 16 * 80));
                LDMX4(bl0, bl1, bl2, bl3, bLoB + ko + (unsigned)(nb * 16 * 80));
                #pragma unroll
                for (int mi = 0; mi < 2; mi++) {
                    MMA16816(acc[mi][nb*2+0], ah[mi][0], ah[mi][1], ah[mi][2], ah[mi][3], bh0, bh1);
                    MMA16816(acc[mi][nb*2+1], ah[mi][0], ah[mi][1], ah[mi][2], ah[mi][3], bh2, bh3);
                    MMA16816(acc[mi][nb*2+0], ah[mi][0], ah[mi][1], ah[mi][2], ah[mi][3], bl0, bl1);
                    MMA16816(acc[mi][nb*2+1], ah[mi][0], ah[mi][1], ah[mi][2], ah[mi][3], bl2, bl3);
                    MMA16816(acc[mi][nb*2+0], al[mi][0], al[mi][1], al[mi][2], al[mi][3], bh0, bh1);
                    MMA16816(acc[mi][nb*2+1], al[mi][0], al[mi][1], al[mi][2], al[mi][3], bh2, bh3);
                }
            }
        }
        __syncthreads();
        if (kc + 2 < 24) stage(kc + 2, s);
    }

    // ---- epilogue: fragment layout c0,c1 @ row r, cols 2t; c2,c3 @ row r+8 ----
    const bool isGate = (cBase >= 768);
    const int rBase = m0 + warpM + (lane >> 2);
    const int cLane = 2 * (lane & 3);
    #pragma unroll
    for (int mi = 0; mi < 2; mi++) {
        #pragma unroll
        for (int ni = 0; ni < 8; ni++) {
            const int col = cBase + warpN + ni * 8 + cLane;
            const int r0 = rBase + mi * 16;
            if (!isGate) {
                *(float2*)(g_h + (size_t)r0 * 768 + col)       = make_float2(acc[mi][ni][0], acc[mi][ni][1]);
                *(float2*)(g_h + (size_t)(r0 + 8) * 768 + col) = make_float2(acc[mi][ni][2], acc[mi][ni][3]);
            } else {
                const int cg = col - 768;
                const float hb0 = Hb[cg], hb1 = Hb[cg + 1];
                *(float2*)(g_gate + (size_t)r0 * 768 + cg) =
                    make_float2(sigm(acc[mi][ni][0] + hb0), sigm(acc[mi][ni][1] + hb1));
                *(float2*)(g_gate + (size_t)(r0 + 8) * 768 + cg) =
                    make_float2(sigm(acc[mi][ni][2] + hb0), sigm(acc[mi][ni][3] + hb1));
            }
        }
    }
}

// =========================================================================
// Kernel 2: src/dst = <tanh(h[b,h,n,:]), w_src/w_dst>. One warp per row.
// =========================================================================
__global__ __launch_bounds__(256) void srcdst_kernel(
    const float* __restrict__ wsrc, const float* __restrict__ wdst)
{
    const int tid = threadIdx.x, lane = tid & 31, wid = tid >> 5;
    const int gid = blockIdx.x * 8 + wid;          // 0..49151
    const int b = gid / 12288;
    const int r = gid - b * 12288;
    const int h = r >> 11;
    const int n = r & 2047;

    const float4 v  = *(const float4*)(g_h + (size_t)(b*2048 + n)*768 + h*128 + lane*4);
    const float4 ws = *(const float4*)(wsrc + h*128 + lane*4);
    const float4 wd = *(const float4*)(wdst + h*128 + lane*4);
    float t, ss = 0.f, sd = 0.f;
    t = tanhf(v.x); ss += t*ws.x; sd += t*wd.x;
    t = tanhf(v.y); ss += t*ws.y; sd += t*wd.y;
    t = tanhf(v.z); ss += t*ws.z; sd += t*wd.z;
    t = tanhf(v.w); ss += t*ws.w; sd += t*wd.w;
    #pragma unroll
    for (int o = 16; o > 0; o >>= 1) {
        ss += __shfl_xor_sync(0xffffffffu, ss, o);
        sd += __shfl_xor_sync(0xffffffffu, sd, o);
    }
    if (lane == 0) {
        const int idx = (b*6 + h)*2048 + n;
        g_src[idx] = ss; g_dst[idx] = sd;
    }
}

// =========================================================================
// Kernel 3: M[b,h,i] = leaky(src[i] + max_j dst[j]). One block per (b,h).
// =========================================================================
__global__ __launch_bounds__(256) void rowmax_kernel()
{
    __shared__ float red[256];
    const int bh = blockIdx.x, tid = threadIdx.x;
    float m = -3.0e38f;
    for (int n = tid; n < 2048; n += 256) m = fmaxf(m, g_dst[bh*2048 + n]);
    red[tid] = m; __syncthreads();
    for (int s = 128; s > 0; s >>= 1) {
        if (tid < s) red[tid] = fmaxf(red[tid], red[tid + s]);
        __syncthreads();
    }
    const float mx = red[0];
    for (int n = tid; n < 2048; n += 256) {
        float s = g_src[bh*2048 + n] + mx;
        g_M[bh*2048 + n] = fmaxf(s, 0.2f * s);
    }
}

// =========================================================================
// Kernel 3b: pack adj into transposed bitmask g_adjbits[b][word][n].
// =========================================================================
__global__ __launch_bounds__(256) void adjpack_kernel(const int* __restrict__ adj)
{
    const int lane = threadIdx.x & 31, wid = threadIdx.x >> 5;
    const int g = blockIdx.x * 8 + wid;           // word id, 0..524287
    const int b = g >> 17;
    const int rem = g & 131071;
    const int n = rem >> 6;
    const int w = rem & 63;
    const int v = adj[((size_t)(b*2048) + n)*2048 + w*32 + lane];
    const unsigned m = __ballot_sync(0xffffffffu, v != 0);
    if (lane == 0) g_adjbits[((size_t)b*64 + w)*2048 + n] = m;
}

// =========================================================================
// Kernel 4: fused attention, software-pipelined (unchanged from best pass).
// =========================================================================
#define ATTN_SMEM_BYTES 58624

__global__ __launch_bounds__(128) void attn_kernel(
    const float* __restrict__ feat_in,
    const float* __restrict__ bias, float* __restrict__ out)
{
    extern __shared__ __align__(16) float smem[];
    float* Vsm   = smem;            // [2][32][128]
    float* Psm   = smem + 8192;     // [2][32][64]
    float* sDst  = smem + 12288;
    float* sSrc  = smem + 14336;
    float* sM    = sSrc + 64;
    float* sLinv = sM + 64;
    float* lpart = sLinv + 64;      // [2][64]

    const int tid = threadIdx.x;
    const int b = blockIdx.z, h = blockIdx.y;
    const int i0 = blockIdx.x * 64;
    const int bh = b*6 + h;
    const int lane = tid & 31, wid = tid >> 5;

    for (int t = tid; t < 2048; t += 128) sDst[t] = g_dst[bh*2048 + t];
    if (tid < 64) {
        sSrc[tid] = g_src[bh*2048 + i0 + tid];
        sM[tid]   = g_M[bh*2048 + i0 + tid];
    }
    __syncthreads();

    const int il = tid & 63, jh = tid >> 6;
    const float srcv = sSrc[il], Mv = sM[il];
    float psum = 0.f;
    const int ty = tid >> 4, tx = tid & 15;
    const int c0 = tx*4;

    const float* Vg = g_h + (size_t)(b*2048)*768 + h*128;
    const unsigned* abT = g_adjbits + (size_t)b*64*2048 + (i0 + il);

    const unsigned vsBase = (unsigned)__cvta_generic_to_shared(Vsm);
    const unsigned vDstBase = vsBase + (unsigned)(wid*512 + lane*16);
    const float* vSrcBase = Vg + (size_t)wid*768 + lane*4;

    ull acc[8][4];
    #pragma unroll
    for (int i = 0; i < 8; i++)
        #pragma unroll
        for (int q = 0; q < 4; q++) acc[i][q] = 0ull;

    auto stageV = [&](int jt, int buf) {
        const float* src = vSrcBase + (size_t)jt*32*768;
        const unsigned dst = vDstBase + (unsigned)buf*16384u;
        #pragma unroll
        for (int r = 0; r < 8; r++)
            CP_ASYNC16(dst + (unsigned)r*2048u, src + (size_t)r*4*768);
        CP_COMMIT();
    };
    auto buildP = [&](int jt, int buf) {
        const int j0 = jt * 32;
        const unsigned am = abT[jt*2048];
        float* Pb = Psm + buf*2048;
        #pragma unroll
        for (int q = 0; q < 4; q++) {
            const int jb = jh*16 + q*4;
            float s, p;
            s = srcv + sDst[j0 + jb + 0]; s = fmaxf(s, 0.2f*s);
            p = ((am >> (jb+0)) & 1u) ? __expf(s - Mv) : 0.f; psum += p; Pb[(jb+0)*64 + il] = p;
            s = srcv + sDst[j0 + jb + 1]; s = fmaxf(s, 0.2f*s);
            p = ((am >> (jb+1)) & 1u) ? __expf(s - Mv) : 0.f; psum += p; Pb[(jb+1)*64 + il] = p;
            s = srcv + sDst[j0 + jb + 2]; s = fmaxf(s, 0.2f*s);
            p = ((am >> (jb+2)) & 1u) ? __expf(s - Mv) : 0.f; psum += p; Pb[(jb+2)*64 + il] = p;
            s = srcv + sDst[j0 + jb + 3]; s = fmaxf(s, 0.2f*s);
            p = ((am >> (jb+3)) & 1u) ? __expf(s - Mv) : 0.f; psum += p; Pb[(jb+3)*64 + il] = p;
        }
    };

    stageV(0, 0);
    buildP(0, 0);
    CP_WAIT0();
    __syncthreads();

    for (int jt = 0; jt < 64; jt++) {
        const int cur = jt & 1;

        if (jt < 63) {
            stageV(jt + 1, cur ^ 1);
            buildP(jt + 1, cur ^ 1);
        }

        const float* Pc = Psm + cur*2048;
        const float* Vc = Vsm + cur*4096;
        #pragma unroll 4
        for (int j = 0; j < 32; j++) {
            const float4 p0 = *(const float4*)&Pc[j*64 + ty*8];
            const float4 p1 = *(const float4*)&Pc[j*64 + ty*8 + 4];
            const ulonglong2 vA = *(const ulonglong2*)&Vc[j*128 + c0];
            const ulonglong2 vB = *(const ulonglong2*)&Vc[j*128 + 64 + c0];
            ull q;
            q = pk2(p0.x); acc[0][0]=f2(q,vA.x,acc[0][0]); acc[0][1]=f2(q,vA.y,acc[0][1]);
                           acc[0][2]=f2(q,vB.x,acc[0][2]); acc[0][3]=f2(q,vB.y,acc[0][3]);
            q = pk2(p0.y); acc[1][0]=f2(q,vA.x,acc[1][0]); acc[1][1]=f2(q,vA.y,acc[1][1]);
                           acc[1][2]=f2(q,vB.x,acc[1][2]); acc[1][3]=f2(q,vB.y,acc[1][3]);
            q = pk2(p0.z); acc[2][0]=f2(q,vA.x,acc[2][0]); acc[2][1]=f2(q,vA.y,acc[2][1]);
                           acc[2][2]=f2(q,vB.x,acc[2][2]); acc[2][3]=f2(q,vB.y,acc[2][3]);
            q = pk2(p0.w); acc[3][0]=f2(q,vA.x,acc[3][0]); acc[3][1]=f2(q,vA.y,acc[3][1]);
                           acc[3][2]=f2(q,vB.x,acc[3][2]); acc[3][3]=f2(q,vB.y,acc[3][3]);
            q = pk2(p1.x); acc[4][0]=f2(q,vA.x,acc[4][0]); acc[4][1]=f2(q,vA.y,acc[4][1]);
                           acc[4][2]=f2(q,vB.x,acc[4][2]); acc[4][3]=f2(q,vB.y,acc[4][3]);
            q = pk2(p1.y); acc[5][0]=f2(q,vA.x,acc[5][0]); acc[5][1]=f2(q,vA.y,acc[5][1]);
                           acc[5][2]=f2(q,vB.x,acc[5][2]); acc[5][3]=f2(q,vB.y,acc[5][3]);
            q = pk2(p1.z); acc[6][0]=f2(q,vA.x,acc[6][0]); acc[6][1]=f2(q,vA.y,acc[6][1]);
                           acc[6][2]=f2(q,vB.x,acc[6][2]); acc[6][3]=f2(q,vB.y,acc[6][3]);
            q = pk2(p1.w); acc[7][0]=f2(q,vA.x,acc[7][0]); acc[7][1]=f2(q,vA.y,acc[7][1]);
                           acc[7][2]=f2(q,vB.x,acc[7][2]); acc[7][3]=f2(q,vB.y,acc[7][3]);
        }

        if (jt < 63) CP_WAIT0();
        __syncthreads();
    }

    lpart[jh*64 + il] = psum;
    __syncthreads();
    if (tid < 64) sLinv[tid] = 1.0f / (lpart[tid] + lpart[64 + tid]);
    __syncthreads();

    const float4 bv0 = *(const float4*)(bias + c0);
    const float4 bv1 = *(const float4*)(bias + 64 + c0);
    #pragma unroll
    for (int i = 0; i < 8; i++) {
        const int row = ty*8 + i;
        const int n = i0 + row;
        const float linv = sLinv[row];
        const size_t base = ((size_t)(b*2048) + n)*768 + h*128 + c0;
        const float4 x0 = *(const float4*)(feat_in + base);
        const float4 x1 = *(const float4*)(feat_in + base + 64);
        const float4 g0 = *(const float4*)(g_gate + base);
        const float4 g1 = *(const float4*)(g_gate + base + 64);
        float fo, e;
        float4 o0, o1;
        fo = lo32(acc[i][0])*linv + bv0.x; e = (fo > 0.f) ? fo : expm1f(fo); o0.x = x0.x + g0.x*(e - x0.x);
        fo = hi32(acc[i][0])*linv + bv0.y; e = (fo > 0.f) ? fo : expm1f(fo); o0.y = x0.y + g0.y*(e - x0.y);
        fo = lo32(acc[i][1])*linv + bv0.z; e = (fo > 0.f) ? fo : expm1f(fo); o0.z = x0.z + g0.z*(e - x0.z);
        fo = hi32(acc[i][1])*linv + bv0.w; e = (fo > 0.f) ? fo : expm1f(fo); o0.w = x0.w + g0.w*(e - x0.w);
        fo = lo32(acc[i][2])*linv + bv1.x; e = (fo > 0.f) ? fo : expm1f(fo); o1.x = x1.x + g1.x*(e - x1.x);
        fo = hi32(acc[i][2])*linv + bv1.y; e = (fo > 0.f) ? fo : expm1f(fo); o1.y = x1.y + g1.y*(e - x1.y);
        fo = lo32(acc[i][3])*linv + bv1.z; e = (fo > 0.f) ? fo : expm1f(fo); o1.z = x1.z + g1.z*(e - x1.z);
        fo = hi32(acc[i][3])*linv + bv1.w; e = (fo > 0.f) ? fo : expm1f(fo); o1.w = x1.w + g1.w*(e - x1.w);
        *(float4*)(out + base)      = o0;
        *(float4*)(out + base + 64) = o1;
    }
}

extern "C" void kernel_launch(void* const* d_in, const int* in_sizes, int n_in,
                              void* d_out, int out_size) {
    (void)in_sizes; (void)n_in; (void)out_size;
    const float* feat_in = (const float*)d_in[0];
    const int*   adj     = (const int*)d_in[1];
    const float* W       = (const float*)d_in[2];
    const float* bvec    = (const float*)d_in[3];
    const float* w_src   = (const float*)d_in[4];
    const float* w_dst   = (const float*)d_in[5];
    const float* H_w     = (const float*)d_in[6];
    const float* H_b     = (const float*)d_in[7];
    float* out = (float*)d_out;

    cudaFuncSetAttribute(attn_kernel,
                         cudaFuncAttributeMaxDynamicSharedMemorySize, ATTN_SMEM_BYTES);
    cudaFuncSetAttribute(proj_mma,
                         cudaFuncAttributeMaxDynamicSharedMemorySize, PROJ_SMEM_BYTES);

    splitX_kernel<<<6144, 256>>>(feat_in);
    buildB_kernel<<<4608, 256>>>(W, H_w);
    proj_mma<<<dim3(12, 64), 256, PROJ_SMEM_BYTES>>>(H_b);
    adjpack_kernel<<<65536, 256>>>(adj);
    srcdst_kernel<<<6144, 256>>>(w_src, w_dst);
    rowmax_kernel<<<24, 256>>>();
    attn_kernel<<<dim3(32, 6, 4), 128, ATTN_SMEM_BYTES>>>(feat_in, bvec, out);
}

// round 14
// speedup vs baseline: 2.5933x; 1.6075x over previous
#include <cuda_runtime.h>
#include <cuda_bf16.h>
#include <math.h>

typedef unsigned long long ull;

#define Bb 4
#define Nn 2048
#define Dd 768
#define Hh 6
#define Do_ 128

__device__ __align__(16) float g_h[Bb*Nn*Dd];     // per-head projected features, col = h*128+o
__device__ __align__(16) float g_gate[Bb*Nn*Dd];  // sigmoid gate
__device__ float g_src[Bb*Hh*Nn];
__device__ float g_dst[Bb*Hh*Nn];
__device__ float g_M[Bb*Hh*Nn];                   // leaky(src_i + max_j dst_j)
__device__ unsigned g_adjbits[Bb*64*Nn];          // transposed bitmask: [b][word(j/32)][n]

// bf16 split operands for the MMA projection GEMM
__device__ __align__(16) __nv_bfloat16 g_Xhi[Bb*Nn*Dd];
__device__ __align__(16) __nv_bfloat16 g_Xlo[Bb*Nn*Dd];
__device__ __align__(16) __nv_bfloat16 g_Bhi[1536*Dd];   // B[c][i]: c<768 -> W[h][i][o], else H_w row
__device__ __align__(16) __nv_bfloat16 g_Blo[1536*Dd];
// bf16 split copy of g_h for the attention P@V MMA (written by proj epilogue)
__device__ __align__(16) __nv_bfloat16 g_Vhi[Bb*Nn*Dd];
__device__ __align__(16) __nv_bfloat16 g_Vlo[Bb*Nn*Dd];

__device__ __forceinline__ float sigm(float x) { return 1.0f / (1.0f + __expf(-x)); }

#define CP_ASYNC16(dst_u32, src_ptr) \
    asm volatile("cp.async.cg.shared.global [%0], [%1], 16;" :: "r"(dst_u32), "l"(src_ptr))
#define CP_COMMIT()  asm volatile("cp.async.commit_group;" ::: "memory")
#define CP_WAIT0()   asm volatile("cp.async.wait_group 0;" ::: "memory")
#define CP_WAIT1()   asm volatile("cp.async.wait_group 1;" ::: "memory")

__device__ __forceinline__ unsigned smem_u32(const void* p) {
    return (unsigned)__cvta_generic_to_shared(p);
}

#define LDMX4(r0, r1, r2, r3, addr) \
    asm volatile("ldmatrix.sync.aligned.m8n8.x4.shared.b16 {%0,%1,%2,%3}, [%4];" \
        : "=r"(r0), "=r"(r1), "=r"(r2), "=r"(r3) : "r"(addr))
#define LDMX4T(r0, r1, r2, r3, addr) \
    asm volatile("ldmatrix.sync.aligned.m8n8.x4.trans.shared.b16 {%0,%1,%2,%3}, [%4];" \
        : "=r"(r0), "=r"(r1), "=r"(r2), "=r"(r3) : "r"(addr))

#define MMA16816(d, a0, a1, a2, a3, b0, b1) \
    asm volatile("mma.sync.aligned.m16n8k16.row.col.f32.bf16.bf16.f32 " \
        "{%0,%1,%2,%3}, {%4,%5,%6,%7}, {%8,%9}, {%0,%1,%2,%3};" \
        : "+f"((d)[0]), "+f"((d)[1]), "+f"((d)[2]), "+f"((d)[3]) \
        : "r"(a0), "r"(a1), "r"(a2), "r"(a3), "r"(b0), "r"(b1))

// =========================================================================
// Prep 1: split X into hi/lo bf16. 4 floats per thread.
// =========================================================================
__global__ __launch_bounds__(256) void splitX_kernel(const float* __restrict__ X)
{
    const int t = blockIdx.x * 256 + threadIdx.x;       // 0..1572863
    const float4 v = ((const float4*)X)[t];
    __nv_bfloat16 h0 = __float2bfloat16(v.x), h1 = __float2bfloat16(v.y);
    __nv_bfloat16 h2 = __float2bfloat16(v.z), h3 = __float2bfloat16(v.w);
    __nv_bfloat16 l0 = __float2bfloat16(v.x - __bfloat162float(h0));
    __nv_bfloat16 l1 = __float2bfloat16(v.y - __bfloat162float(h1));
    __nv_bfloat16 l2 = __float2bfloat16(v.z - __bfloat162float(h2));
    __nv_bfloat16 l3 = __float2bfloat16(v.w - __bfloat162float(h3));
    __nv_bfloat162* Hi = (__nv_bfloat162*)g_Xhi;
    __nv_bfloat162* Lo = (__nv_bfloat162*)g_Xlo;
    Hi[t*2]   = __nv_bfloat162(h0, h1);  Hi[t*2+1] = __nv_bfloat162(h2, h3);
    Lo[t*2]   = __nv_bfloat162(l0, l1);  Lo[t*2+1] = __nv_bfloat162(l2, l3);
}

// =========================================================================
// Prep 2: build concatenated B [1536 x 768] K-major, split hi/lo.
// =========================================================================
__global__ __launch_bounds__(256) void buildB_kernel(
    const float* __restrict__ W, const float* __restrict__ Hw)
{
    const int t = blockIdx.x * 256 + threadIdx.x;       // 0..1179647
    const int c = t / 768, i = t - c * 768;
    float v;
    if (c < 768) v = W[(((size_t)(c >> 7) * 768 + i) * 128) + (c & 127)];
    else         v = Hw[(size_t)(c - 768) * 768 + i];
    const __nv_bfloat16 hi = __float2bfloat16(v);
    g_Bhi[t] = hi;
    g_Blo[t] = __float2bfloat16(v - __bfloat162float(hi));
}

// =========================================================================
// Kernel 1: bf16 3-term split GEMM via ldmatrix + mma.sync (HMMA).
// C[8192,1536] = X*B^T; BM=128 BN=128 BK=32, 256 thr, warp tile 32x64.
// Epilogue also writes bf16 hi/lo split of g_h (V operand for attention).
// =========================================================================
#define PROJ_SMEM_BYTES (81920 + 1024)

__global__ __launch_bounds__(256, 2) void proj_mma(const float* __restrict__ Hb)
{
    extern __shared__ __align__(16) char dynsm[];

    const int tid  = threadIdx.x;
    const int wid  = tid >> 5, lane = tid & 31;
    const int cBase = blockIdx.x * 128;     // 0..1408
    const int m0    = blockIdx.y * 128;

    const unsigned dynBase = (smem_u32(dynsm) + 1023u) & ~1023u;

    const int warpM = (wid & 3) * 32;       // 4 warps over M
    const int warpN = (wid >> 2) * 64;      // 2 warps over N

    const __nv_bfloat16* baseSrc[4] = {
        g_Xhi + (size_t)m0 * 768, g_Xlo + (size_t)m0 * 768,
        g_Bhi + (size_t)cBase * 768, g_Blo + (size_t)cBase * 768 };

    auto stage = [&](int kc, int s) {
        const unsigned sb = dynBase + (unsigned)s * 40960u;
        #pragma unroll
        for (int rep = 0; rep < 8; rep++) {
            const int u = rep * 256 + tid;          // 0..2047
            const int T = u >> 9;
            const int rc = u & 511;
            const int row = rc >> 2, c16 = rc & 3;
            CP_ASYNC16(sb + (unsigned)(T * 10240 + row * 80 + c16 * 16),
                       (const char*)(baseSrc[T] + (size_t)row * 768 + kc * 32 + c16 * 8));
        }
        CP_COMMIT();
    };

    const int grp = lane >> 3, l7 = lane & 7;
    const unsigned aLane = (unsigned)(((grp & 1) * 8 + l7) * 80 + (grp >> 1) * 16);
    const unsigned bLane = (unsigned)(((grp >> 1) * 8 + l7) * 80 + (grp & 1) * 16);

    float acc[2][8][4];
    #pragma unroll
    for (int mi = 0; mi < 2; mi++)
        #pragma unroll
        for (int ni = 0; ni < 8; ni++)
            #pragma unroll
            for (int q = 0; q < 4; q++) acc[mi][ni][q] = 0.f;

    stage(0, 0);
    stage(1, 1);

    for (int kc = 0; kc < 24; kc++) {
        const int s = kc & 1;
        CP_WAIT1();
        __syncthreads();

        const unsigned sb  = dynBase + (unsigned)s * 40960u;
        const unsigned aHiB = sb            + (unsigned)(warpM * 80) + aLane;
        const unsigned aLoB = sb + 10240u   + (unsigned)(warpM * 80) + aLane;
        const unsigned bHiB = sb + 20480u   + (unsigned)(warpN * 80) + bLane;
        const unsigned bLoB = sb + 30720u   + (unsigned)(warpN * 80) + bLane;

        #pragma unroll
        for (int ks = 0; ks < 2; ks++) {
            const unsigned ko = (unsigned)(ks * 32);
            unsigned ah[2][4], al[2][4];
            LDMX4(ah[0][0], ah[0][1], ah[0][2], ah[0][3], aHiB + ko);
            LDMX4(ah[1][0], ah[1][1], ah[1][2], ah[1][3], aHiB + ko + 16u*80u);
            LDMX4(al[0][0], al[0][1], al[0][2], al[0][3], aLoB + ko);
            LDMX4(al[1][0], al[1][1], al[1][2], al[1][3], aLoB + ko + 16u*80u);
            #pragma unroll
            for (int nb = 0; nb < 4; nb++) {
                unsigned bh0, bh1, bh2, bh3, bl0, bl1, bl2, bl3;
                LDMX4(bh0, bh1, bh2, bh3, bHiB + ko + (unsigned)(nb * 16 * 80));
                LDMX4(bl0, bl1, bl2, bl3, bLoB + ko + (unsigned)(nb * 16 * 80));
                #pragma unroll
                for (int mi = 0; mi < 2; mi++) {
                    MMA16816(acc[mi][nb*2+0], ah[mi][0], ah[mi][1], ah[mi][2], ah[mi][3], bh0, bh1);
                    MMA16816(acc[mi][nb*2+1], ah[mi][0], ah[mi][1], ah[mi][2], ah[mi][3], bh2, bh3);
                    MMA16816(acc[mi][nb*2+0], ah[mi][0], ah[mi][1], ah[mi][2], ah[mi][3], bl0, bl1);
                    MMA16816(acc[mi][nb*2+1], ah[mi][0], ah[mi][1], ah[mi][2], ah[mi][3], bl2, bl3);
                    MMA16816(acc[mi][nb*2+0], al[mi][0], al[mi][1], al[mi][2], al[mi][3], bh0, bh1);
                    MMA16816(acc[mi][nb*2+1], al[mi][0], al[mi][1], al[mi][2], al[mi][3], bh2, bh3);
                }
            }
        }
        __syncthreads();
        if (kc + 2 < 24) stage(kc + 2, s);
    }

    const bool isGate = (cBase >= 768);
    const int rBase = m0 + warpM + (lane >> 2);
    const int cLane = 2 * (lane & 3);
    #pragma unroll
    for (int mi = 0; mi < 2; mi++) {
        #pragma unroll
        for (int ni = 0; ni < 8; ni++) {
            const int col = cBase + warpN + ni * 8 + cLane;
            const int r0 = rBase + mi * 16;
            if (!isGate) {
                const float v0 = acc[mi][ni][0], v1 = acc[mi][ni][1];
                const float v2 = acc[mi][ni][2], v3 = acc[mi][ni][3];
                *(float2*)(g_h + (size_t)r0 * 768 + col)       = make_float2(v0, v1);
                *(float2*)(g_h + (size_t)(r0 + 8) * 768 + col) = make_float2(v2, v3);
                // bf16 split V copy for attention
                __nv_bfloat16 h0 = __float2bfloat16(v0), h1 = __float2bfloat16(v1);
                __nv_bfloat16 h2 = __float2bfloat16(v2), h3 = __float2bfloat16(v3);
                *(__nv_bfloat162*)(g_Vhi + (size_t)r0 * 768 + col) = __nv_bfloat162(h0, h1);
                *(__nv_bfloat162*)(g_Vhi + (size_t)(r0 + 8) * 768 + col) = __nv_bfloat162(h2, h3);
                *(__nv_bfloat162*)(g_Vlo + (size_t)r0 * 768 + col) =
                    __nv_bfloat162(__float2bfloat16(v0 - __bfloat162float(h0)),
                                   __float2bfloat16(v1 - __bfloat162float(h1)));
                *(__nv_bfloat162*)(g_Vlo + (size_t)(r0 + 8) * 768 + col) =
                    __nv_bfloat162(__float2bfloat16(v2 - __bfloat162float(h2)),
                                   __float2bfloat16(v3 - __bfloat162float(h3)));
            } else {
                const int cg = col - 768;
                const float hb0 = Hb[cg], hb1 = Hb[cg + 1];
                *(float2*)(g_gate + (size_t)r0 * 768 + cg) =
                    make_float2(sigm(acc[mi][ni][0] + hb0), sigm(acc[mi][ni][1] + hb1));
                *(float2*)(g_gate + (size_t)(r0 + 8) * 768 + cg) =
                    make_float2(sigm(acc[mi][ni][2] + hb0), sigm(acc[mi][ni][3] + hb1));
            }
        }
    }
}

// =========================================================================
// Kernel 2: src/dst = <tanh(h[b,h,n,:]), w_src/w_dst>. One warp per row.
// =========================================================================
__global__ __launch_bounds__(256) void srcdst_kernel(
    const float* __restrict__ wsrc, const float* __restrict__ wdst)
{
    const int tid = threadIdx.x, lane = tid & 31, wid = tid >> 5;
    const int gid = blockIdx.x * 8 + wid;          // 0..49151
    const int b = gid / 12288;
    const int r = gid - b * 12288;
    const int h = r >> 11;
    const int n = r & 2047;

    const float4 v  = *(const float4*)(g_h + (size_t)(b*2048 + n)*768 + h*128 + lane*4);
    const float4 ws = *(const float4*)(wsrc + h*128 + lane*4);
    const float4 wd = *(const float4*)(wdst + h*128 + lane*4);
    float t, ss = 0.f, sd = 0.f;
    t = tanhf(v.x); ss += t*ws.x; sd += t*wd.x;
    t = tanhf(v.y); ss += t*ws.y; sd += t*wd.y;
    t = tanhf(v.z); ss += t*ws.z; sd += t*wd.z;
    t = tanhf(v.w); ss += t*ws.w; sd += t*wd.w;
    #pragma unroll
    for (int o = 16; o > 0; o >>= 1) {
        ss += __shfl_xor_sync(0xffffffffu, ss, o);
        sd += __shfl_xor_sync(0xffffffffu, sd, o);
    }
    if (lane == 0) {
        const int idx = (b*6 + h)*2048 + n;
        g_src[idx] = ss; g_dst[idx] = sd;
    }
}

// =========================================================================
// Kernel 3: M[b,h,i] = leaky(src[i] + max_j dst[j]). One block per (b,h).
// =========================================================================
__global__ __launch_bounds__(256) void rowmax_kernel()
{
    __shared__ float red[256];
    const int bh = blockIdx.x, tid = threadIdx.x;
    float m = -3.0e38f;
    for (int n = tid; n < 2048; n += 256) m = fmaxf(m, g_dst[bh*2048 + n]);
    red[tid] = m; __syncthreads();
    for (int s = 128; s > 0; s >>= 1) {
        if (tid < s) red[tid] = fmaxf(red[tid], red[tid + s]);
        __syncthreads();
    }
    const float mx = red[0];
    for (int n = tid; n < 2048; n += 256) {
        float s = g_src[bh*2048 + n] + mx;
        g_M[bh*2048 + n] = fmaxf(s, 0.2f * s);
    }
}

// =========================================================================
// Kernel 3b: pack adj into transposed bitmask. Warp handles 8 words for one
// (b,n): 8 strided coalesced LDGs (MLP=8) then 8 ballots.
// =========================================================================
__global__ __launch_bounds__(256) void adjpack_kernel(const int* __restrict__ adj)
{
    const int lane = threadIdx.x & 31, wid = threadIdx.x >> 5;
    const int g = blockIdx.x * 8 + wid;           // group id, 0..65535
    const int b = g >> 14;                         // / (2048*8)
    const int rem = g & 16383;
    const int n = rem >> 3;
    const int grp = rem & 7;
    const int* base = adj + ((size_t)(b*2048) + n)*2048 + grp*256 + lane;
    int v[8];
    #pragma unroll
    for (int k = 0; k < 8; k++) v[k] = base[k*32];
    #pragma unroll
    for (int k = 0; k < 8; k++) {
        const unsigned m = __ballot_sync(0xffffffffu, v[k] != 0);
        if (lane == 0) g_adjbits[((size_t)b*64 + grp*8 + k)*2048 + n] = m;
    }
}

// =========================================================================
// Kernel 4: fused attention with HMMA P@V (3-term bf16 split).
// Block = (64 i-rows, h, b), 128 threads = 4 warps, warp covers n32 slice.
// Per 32-j tile: build P fp32 -> split bf16 hi/lo into smem A-tiles; V hi/lo
// staged via cp.async from g_Vhi/g_Vlo; mma.sync accumulates fp32.
// Smem layout (bytes from base):
//   V buffers: 2 x [hi 32x272 | lo 32x272] = 2 x 17408      @ 0
//   P buffers: 2 x [hi 64x80  | lo 64x80 ] = 2 x 10240      @ 34816
//   sDst 2048f @ 55296 ; sSrc @ 63488 ; sM @ 63744 ; sLinv @ 64000 ; lpart @ 64256
// =========================================================================
#define ATTN_SMEM_BYTES 64768

__global__ __launch_bounds__(128) void attn_kernel(
    const float* __restrict__ feat_in,
    const float* __restrict__ bias, float* __restrict__ out)
{
    extern __shared__ __align__(16) char dynsm[];
    const unsigned smBase = smem_u32(dynsm);
    const unsigned Vb0 = smBase;
    const unsigned Pb0 = smBase + 34816u;
    float* sDst  = (float*)(dynsm + 55296);
    float* sSrc  = (float*)(dynsm + 63488);
    float* sM    = (float*)(dynsm + 63744);
    float* sLinv = (float*)(dynsm + 64000);
    float* lpart = (float*)(dynsm + 64256);

    const int tid = threadIdx.x;
    const int b = blockIdx.z, h = blockIdx.y;
    const int i0 = blockIdx.x * 64;
    const int bh = b*6 + h;
    const int lane = tid & 31, wid = tid >> 5;

    for (int t = tid; t < 2048; t += 128) sDst[t] = g_dst[bh*2048 + t];
    if (tid < 64) {
        sSrc[tid] = g_src[bh*2048 + i0 + tid];
        sM[tid]   = g_M[bh*2048 + i0 + tid];
    }
    __syncthreads();

    const int il = tid & 63, jh = tid >> 6;        // P-build role
    const float srcv = sSrc[il], Mv = sM[il];
    float psum = 0.f;

    const unsigned* abT = g_adjbits + (size_t)b*64*2048 + (i0 + il);
    const size_t vRowBase = (size_t)(b*2048)*768 + h*128;

    // ldmatrix lane offsets
    const int grp = lane >> 3, l7 = lane & 7;
    const unsigned aOff = (unsigned)(((grp & 1) * 8 + l7) * 80 + (grp >> 1) * 16);
    const unsigned vOff = (unsigned)(((grp & 1) * 8 + l7) * 272 + (grp >> 1) * 16);
    const unsigned nW = (unsigned)(wid * 32 * 2);  // warp's n-slice byte offset

    float acc[4][4][4];
    #pragma unroll
    for (int mi = 0; mi < 4; mi++)
        #pragma unroll
        for (int ni = 0; ni < 4; ni++)
            #pragma unroll
            for (int q = 0; q < 4; q++) acc[mi][ni][q] = 0.f;

    // ---- stage V tile (hi+lo) for j-tile jt into buffer buf ----
    auto stageV = [&](int jt, int buf) {
        const unsigned vb = Vb0 + (unsigned)buf * 17408u;
        const int j0 = jt * 32;
        #pragma unroll
        for (int rep = 0; rep < 8; rep++) {
            const int u = rep * 128 + tid;          // 0..1023
            const int mat = u >> 9;                  // 0 hi, 1 lo
            const int rc = u & 511;
            const int row = rc >> 4, c16 = rc & 15;
            const __nv_bfloat16* src = (mat ? g_Vlo : g_Vhi) + vRowBase
                                       + (size_t)(j0 + row) * 768 + c16 * 8;
            CP_ASYNC16(vb + (unsigned)(mat * 8704 + row * 272 + c16 * 16), (const char*)src);
        }
        CP_COMMIT();
    };

    // ---- build P (fp32 exp, bf16 hi/lo split) for j-tile jt into buffer buf ----
    auto buildP = [&](int jt, int buf) {
        const int j0 = jt * 32;
        const unsigned am = abT[jt*2048];
        __nv_bfloat162* Ph = (__nv_bfloat162*)(dynsm + 34816 + buf * 10240 + il * 80);
        __nv_bfloat162* Pl = (__nv_bfloat162*)(dynsm + 34816 + buf * 10240 + 5120 + il * 80);
        #pragma unroll
        for (int q = 0; q < 8; q++) {
            const int jb = jh*16 + q*2;
            float s0 = srcv + sDst[j0 + jb + 0]; s0 = fmaxf(s0, 0.2f*s0);
            float s1 = srcv + sDst[j0 + jb + 1]; s1 = fmaxf(s1, 0.2f*s1);
            float p0 = ((am >> (jb+0)) & 1u) ? __expf(s0 - Mv) : 0.f;
            float p1 = ((am >> (jb+1)) & 1u) ? __expf(s1 - Mv) : 0.f;
            psum += p0 + p1;
            __nv_bfloat16 h0 = __float2bfloat16(p0), h1 = __float2bfloat16(p1);
            Ph[jb >> 1] = __nv_bfloat162(h0, h1);
            Pl[jb >> 1] = __nv_bfloat162(__float2bfloat16(p0 - __bfloat162float(h0)),
                                         __float2bfloat16(p1 - __bfloat162float(h1)));
        }
    };

    stageV(0, 0);
    buildP(0, 0);
    CP_WAIT0();
    __syncthreads();

    for (int jt = 0; jt < 64; jt++) {
        const int cur = jt & 1;

        if (jt < 63) {
            stageV(jt + 1, cur ^ 1);
            buildP(jt + 1, cur ^ 1);
        }

        const unsigned vb = Vb0 + (unsigned)cur * 17408u;
        const unsigned pb = Pb0 + (unsigned)cur * 10240u;

        #pragma unroll
        for (int ks = 0; ks < 2; ks++) {
            // V fragments: two n16 groups for this warp's n32, hi and lo
            const unsigned vk = vb + (unsigned)(ks * 16 * 272) + vOff + nW;
            unsigned vh0[4], vh1[4], vl0[4], vl1[4];
            LDMX4T(vh0[0], vh0[1], vh0[2], vh0[3], vk);
            LDMX4T(vh1[0], vh1[1], vh1[2], vh1[3], vk + 32u);
            LDMX4T(vl0[0], vl0[1], vl0[2], vl0[3], vk + 8704u);
            LDMX4T(vl1[0], vl1[1], vl1[2], vl1[3], vk + 8704u + 32u);
            #pragma unroll
            for (int mi = 0; mi < 4; mi++) {
                const unsigned pa = pb + (unsigned)(mi * 16 * 80 + ks * 32) + aOff;
                unsigned ph[4], pl[4];
                LDMX4(ph[0], ph[1], ph[2], ph[3], pa);
                LDMX4(pl[0], pl[1], pl[2], pl[3], pa + 5120u);
                MMA16816(acc[mi][0], ph[0], ph[1], ph[2], ph[3], vh0[0], vh0[1]);
                MMA16816(acc[mi][1], ph[0], ph[1], ph[2], ph[3], vh0[2], vh0[3]);
                MMA16816(acc[mi][2], ph[0], ph[1], ph[2], ph[3], vh1[0], vh1[1]);
                MMA16816(acc[mi][3], ph[0], ph[1], ph[2], ph[3], vh1[2], vh1[3]);
                MMA16816(acc[mi][0], ph[0], ph[1], ph[2], ph[3], vl0[0], vl0[1]);
                MMA16816(acc[mi][1], ph[0], ph[1], ph[2], ph[3], vl0[2], vl0[3]);
                MMA16816(acc[mi][2], ph[0], ph[1], ph[2], ph[3], vl1[0], vl1[1]);
                MMA16816(acc[mi][3], ph[0], ph[1], ph[2], ph[3], vl1[2], vl1[3]);
                MMA16816(acc[mi][0], pl[0], pl[1], pl[2], pl[3], vh0[0], vh0[1]);
                MMA16816(acc[mi][1], pl[0], pl[1], pl[2], pl[3], vh0[2], vh0[3]);
                MMA16816(acc[mi][2], pl[0], pl[1], pl[2], pl[3], vh1[0], vh1[1]);
                MMA16816(acc[mi][3], pl[0], pl[1], pl[2], pl[3], vh1[2], vh1[3]);
            }
        }

        if (jt < 63) CP_WAIT0();
        __syncthreads();
    }

    // softmax denominators
    lpart[jh*64 + il] = psum;
    __syncthreads();
    if (tid < 64) sLinv[tid] = 1.0f / (lpart[tid] + lpart[64 + tid]);
    __syncthreads();

    // epilogue: /l + bias, ELU, gated residual
    const int rL = lane >> 2, cL = (lane & 3) * 2;
    #pragma unroll
    for (int mi = 0; mi < 4; mi++) {
        const float linv0 = sLinv[mi*16 + rL];
        const float linv1 = sLinv[mi*16 + rL + 8];
        #pragma unroll
        for (int ni = 0; ni < 4; ni++) {
            const int cb = wid*32 + ni*8 + cL;       // 0..127 within head
            const int col = h*128 + cb;
            const float b0 = bias[cb], b1 = bias[cb + 1];
            #pragma unroll
            for (int half = 0; half < 2; half++) {
                const int nrow = i0 + mi*16 + rL + half*8;
                const float linv = half ? linv1 : linv0;
                const size_t base = ((size_t)(b*2048) + nrow)*768 + col;
                const float2 x = *(const float2*)(feat_in + base);
                const float2 g = *(const float2*)(g_gate + base);
                float fo0 = acc[mi][ni][half*2+0]*linv + b0;
                float fo1 = acc[mi][ni][half*2+1]*linv + b1;
                const float e0 = (fo0 > 0.f) ? fo0 : expm1f(fo0);
                const float e1 = (fo1 > 0.f) ? fo1 : expm1f(fo1);
                *(float2*)(out + base) =
                    make_float2(x.x + g.x*(e0 - x.x), x.y + g.y*(e1 - x.y));
            }
        }
    }
}

extern "C" void kernel_launch(void* const* d_in, const int* in_sizes, int n_in,
                              void* d_out, int out_size) {
    (void)in_sizes; (void)n_in; (void)out_size;
    const float* feat_in = (const float*)d_in[0];
    const int*   adj     = (const int*)d_in[1];
    const float* W       = (const float*)d_in[2];
    const float* bvec    = (const float*)d_in[3];
    const float* w_src   = (const float*)d_in[4];
    const float* w_dst   = (const float*)d_in[5];
    const float* H_w     = (const float*)d_in[6];
    const float* H_b     = (const float*)d_in[7];
    float* out = (float*)d_out;

    cudaFuncSetAttribute(attn_kernel,
                         cudaFuncAttributeMaxDynamicSharedMemorySize, ATTN_SMEM_BYTES);
    cudaFuncSetAttribute(proj_mma,
                         cudaFuncAttributeMaxDynamicSharedMemorySize, PROJ_SMEM_BYTES);

    splitX_kernel<<<6144, 256>>>(feat_in);
    buildB_kernel<<<4608, 256>>>(W, H_w);
    proj_mma<<<dim3(12, 64), 256, PROJ_SMEM_BYTES>>>(H_b);
    adjpack_kernel<<<8192, 256>>>(adj);
    srcdst_kernel<<<6144, 256>>>(w_src, w_dst);
    rowmax_kernel<<<24, 256>>>();
    attn_kernel<<<dim3(32, 6, 4), 128, ATTN_SMEM_BYTES>>>(feat_in, bvec, out);
}

// round 15
// speedup vs baseline: 3.3538x; 1.2933x over previous
#include <cuda_runtime.h>
#include <cuda_bf16.h>
#include <cuda_fp16.h>
#include <math.h>

typedef unsigned long long ull;

#define Bb 4
#define Nn 2048
#define Dd 768
#define Hh 6
#define Do_ 128

__device__ __align__(16) float g_h[Bb*Nn*Dd];     // per-head projected features, col = h*128+o
__device__ __align__(16) float g_gate[Bb*Nn*Dd];  // sigmoid gate
__device__ float g_src[Bb*Hh*Nn];
__device__ float g_dst[Bb*Hh*Nn];
__device__ float g_M[Bb*Hh*Nn];                   // leaky(src_i + max_j dst_j)
__device__ unsigned g_adjbits[Bb*64*Nn];          // transposed bitmask: [b][word(j/32)][n]

// fp16 split operands for the MMA projection GEMM
__device__ __align__(16) __half g_Xhi[Bb*Nn*Dd];
__device__ __align__(16) __half g_Xlo[Bb*Nn*Dd];
__device__ __align__(16) __half g_Bh[1536*Dd];    // B[c][i]: c<768 -> W[h][i][o], else H_w row
// fp16 copy of g_h for the attention P@V MMA (written by proj epilogue)
__device__ __align__(16) __half g_Vf16[Bb*Nn*Dd];

__device__ __forceinline__ float sigm(float x) { return 1.0f / (1.0f + __expf(-x)); }

#define CP_ASYNC16(dst_u32, src_ptr) \
    asm volatile("cp.async.cg.shared.global [%0], [%1], 16;" :: "r"(dst_u32), "l"(src_ptr))
#define CP_COMMIT()  asm volatile("cp.async.commit_group;" ::: "memory")
#define CP_WAIT0()   asm volatile("cp.async.wait_group 0;" ::: "memory")
#define CP_WAIT1()   asm volatile("cp.async.wait_group 1;" ::: "memory")

__device__ __forceinline__ unsigned smem_u32(const void* p) {
    return (unsigned)__cvta_generic_to_shared(p);
}

#define LDMX4(r0, r1, r2, r3, addr) \
    asm volatile("ldmatrix.sync.aligned.m8n8.x4.shared.b16 {%0,%1,%2,%3}, [%4];" \
        : "=r"(r0), "=r"(r1), "=r"(r2), "=r"(r3) : "r"(addr))
#define LDMX4T(r0, r1, r2, r3, addr) \
    asm volatile("ldmatrix.sync.aligned.m8n8.x4.trans.shared.b16 {%0,%1,%2,%3}, [%4];" \
        : "=r"(r0), "=r"(r1), "=r"(r2), "=r"(r3) : "r"(addr))

#define MMAH(d, a0, a1, a2, a3, b0, b1) \
    asm volatile("mma.sync.aligned.m16n8k16.row.col.f32.f16.f16.f32 " \
        "{%0,%1,%2,%3}, {%4,%5,%6,%7}, {%8,%9}, {%0,%1,%2,%3};" \
        : "+f"((d)[0]), "+f"((d)[1]), "+f"((d)[2]), "+f"((d)[3]) \
        : "r"(a0), "r"(a1), "r"(a2), "r"(a3), "r"(b0), "r"(b1))

// =========================================================================
// Prep 1: split X into hi/lo fp16. 4 floats per thread.
// =========================================================================
__global__ __launch_bounds__(256) void splitX_kernel(const float* __restrict__ X)
{
    const int t = blockIdx.x * 256 + threadIdx.x;       // 0..1572863
    const float4 v = ((const float4*)X)[t];
    const __half h0 = __float2half_rn(v.x), h1 = __float2half_rn(v.y);
    const __half h2 = __float2half_rn(v.z), h3 = __float2half_rn(v.w);
    const __half l0 = __float2half_rn(v.x - __half2float(h0));
    const __half l1 = __float2half_rn(v.y - __half2float(h1));
    const __half l2 = __float2half_rn(v.z - __half2float(h2));
    const __half l3 = __float2half_rn(v.w - __half2float(h3));
    __half2* Hi = (__half2*)g_Xhi;
    __half2* Lo = (__half2*)g_Xlo;
    Hi[t*2]   = __halves2half2(h0, h1);  Hi[t*2+1] = __halves2half2(h2, h3);
    Lo[t*2]   = __halves2half2(l0, l1);  Lo[t*2+1] = __halves2half2(l2, l3);
}

// =========================================================================
// Prep 2: build concatenated B [1536 x 768] K-major, single fp16.
// c<768: B[c][i] = W[h=c>>7][i][o=c&127]; c>=768: B[c][i] = H_w[c-768][i].
// =========================================================================
__global__ __launch_bounds__(256) void buildB_kernel(
    const float* __restrict__ W, const float* __restrict__ Hw)
{
    const int t = blockIdx.x * 256 + threadIdx.x;       // 0..1179647
    const int c = t / 768, i = t - c * 768;
    float v;
    if (c < 768) v = W[(((size_t)(c >> 7) * 768 + i) * 128) + (c & 127)];
    else         v = Hw[(size_t)(c - 768) * 768 + i];
    g_Bh[t] = __float2half_rn(v);
}

// =========================================================================
// Kernel 1: fp16 2-term split GEMM via ldmatrix + mma.sync (HMMA).
// C[8192,1536] = (Xhi+Xlo)*Bh^T; BM=128 BN=128 BK=32, 256 thr, warp 32x64.
// Smem rows 64B data padded to 80B (bank stride 5 mod 8, conflict-free).
// Stage = [Xhi|Xlo|Bh] x 128 rows x 80B = 30720B; 2 stages.
// Epilogue writes g_h fp32 + single-fp16 g_Vf16 (V operand for attention).
// =========================================================================
#define PROJ_SMEM_BYTES (61440 + 1024)

__global__ __launch_bounds__(256, 2) void proj_mma(const float* __restrict__ Hb)
{
    extern __shared__ __align__(16) char dynsm[];

    const int tid  = threadIdx.x;
    const int wid  = tid >> 5, lane = tid & 31;
    const int cBase = blockIdx.x * 128;     // 0..1408
    const int m0    = blockIdx.y * 128;

    const unsigned dynBase = (smem_u32(dynsm) + 1023u) & ~1023u;

    const int warpM = (wid & 3) * 32;       // 4 warps over M
    const int warpN = (wid >> 2) * 64;      // 2 warps over N

    const __half* baseSrc[3] = {
        g_Xhi + (size_t)m0 * 768, g_Xlo + (size_t)m0 * 768,
        g_Bh + (size_t)cBase * 768 };

    auto stage = [&](int kc, int s) {
        const unsigned sb = dynBase + (unsigned)s * 30720u;
        #pragma unroll
        for (int rep = 0; rep < 6; rep++) {
            const int u = rep * 256 + tid;          // 0..1535
            const int T = u >> 9;
            const int rc = u & 511;
            const int row = rc >> 2, c16 = rc & 3;
            CP_ASYNC16(sb + (unsigned)(T * 10240 + row * 80 + c16 * 16),
                       (const char*)(baseSrc[T] + (size_t)row * 768 + kc * 32 + c16 * 8));
        }
        CP_COMMIT();
    };

    const int grp = lane >> 3, l7 = lane & 7;
    const unsigned aLane = (unsigned)(((grp & 1) * 8 + l7) * 80 + (grp >> 1) * 16);
    const unsigned bLane = (unsigned)(((grp >> 1) * 8 + l7) * 80 + (grp & 1) * 16);

    float acc[2][8][4];
    #pragma unroll
    for (int mi = 0; mi < 2; mi++)
        #pragma unroll
        for (int ni = 0; ni < 8; ni++)
            #pragma unroll
            for (int q = 0; q < 4; q++) acc[mi][ni][q] = 0.f;

    stage(0, 0);
    stage(1, 1);

    for (int kc = 0; kc < 24; kc++) {
        const int s = kc & 1;
        CP_WAIT1();
        __syncthreads();

        const unsigned sb   = dynBase + (unsigned)s * 30720u;
        const unsigned aHiB = sb            + (unsigned)(warpM * 80) + aLane;
        const unsigned aLoB = sb + 10240u   + (unsigned)(warpM * 80) + aLane;
        const unsigned bHiB = sb + 20480u   + (unsigned)(warpN * 80) + bLane;

        #pragma unroll
        for (int ks = 0; ks < 2; ks++) {
            const unsigned ko = (unsigned)(ks * 32);
            unsigned ah[2][4], al[2][4];
            LDMX4(ah[0][0], ah[0][1], ah[0][2], ah[0][3], aHiB + ko);
            LDMX4(ah[1][0], ah[1][1], ah[1][2], ah[1][3], aHiB + ko + 16u*80u);
            LDMX4(al[0][0], al[0][1], al[0][2], al[0][3], aLoB + ko);
            LDMX4(al[1][0], al[1][1], al[1][2], al[1][3], aLoB + ko + 16u*80u);
            #pragma unroll
            for (int nb = 0; nb < 4; nb++) {
                unsigned bh0, bh1, bh2, bh3;
                LDMX4(bh0, bh1, bh2, bh3, bHiB + ko + (unsigned)(nb * 16 * 80));
                #pragma unroll
                for (int mi = 0; mi < 2; mi++) {
                    MMAH(acc[mi][nb*2+0], ah[mi][0], ah[mi][1], ah[mi][2], ah[mi][3], bh0, bh1);
                    MMAH(acc[mi][nb*2+1], ah[mi][0], ah[mi][1], ah[mi][2], ah[mi][3], bh2, bh3);
                    MMAH(acc[mi][nb*2+0], al[mi][0], al[mi][1], al[mi][2], al[mi][3], bh0, bh1);
                    MMAH(acc[mi][nb*2+1], al[mi][0], al[mi][1], al[mi][2], al[mi][3], bh2, bh3);
                }
            }
        }
        __syncthreads();
        if (kc + 2 < 24) stage(kc + 2, s);
    }

    const bool isGate = (cBase >= 768);
    const int rBase = m0 + warpM + (lane >> 2);
    const int cLane = 2 * (lane & 3);
    #pragma unroll
    for (int mi = 0; mi < 2; mi++) {
        #pragma unroll
        for (int ni = 0; ni < 8; ni++) {
            const int col = cBase + warpN + ni * 8 + cLane;
            const int r0 = rBase + mi * 16;
            if (!isGate) {
                const float v0 = acc[mi][ni][0], v1 = acc[mi][ni][1];
                const float v2 = acc[mi][ni][2], v3 = acc[mi][ni][3];
                *(float2*)(g_h + (size_t)r0 * 768 + col)       = make_float2(v0, v1);
                *(float2*)(g_h + (size_t)(r0 + 8) * 768 + col) = make_float2(v2, v3);
                *(__half2*)(g_Vf16 + (size_t)r0 * 768 + col)       = __floats2half2_rn(v0, v1);
                *(__half2*)(g_Vf16 + (size_t)(r0 + 8) * 768 + col) = __floats2half2_rn(v2, v3);
            } else {
                const int cg = col - 768;
                const float hb0 = Hb[cg], hb1 = Hb[cg + 1];
                *(float2*)(g_gate + (size_t)r0 * 768 + cg) =
                    make_float2(sigm(acc[mi][ni][0] + hb0), sigm(acc[mi][ni][1] + hb1));
                *(float2*)(g_gate + (size_t)(r0 + 8) * 768 + cg) =
                    make_float2(sigm(acc[mi][ni][2] + hb0), sigm(acc[mi][ni][3] + hb1));
            }
        }
    }
}

// =========================================================================
// Kernel 2: src/dst = <tanh(h[b,h,n,:]), w_src/w_dst>. One warp per row.
// =========================================================================
__global__ __launch_bounds__(256) void srcdst_kernel(
    const float* __restrict__ wsrc, const float* __restrict__ wdst)
{
    const int tid = threadIdx.x, lane = tid & 31, wid = tid >> 5;
    const int gid = blockIdx.x * 8 + wid;          // 0..49151
    const int b = gid / 12288;
    const int r = gid - b * 12288;
    const int h = r >> 11;
    const int n = r & 2047;

    const float4 v  = *(const float4*)(g_h + (size_t)(b*2048 + n)*768 + h*128 + lane*4);
    const float4 ws = *(const float4*)(wsrc + h*128 + lane*4);
    const float4 wd = *(const float4*)(wdst + h*128 + lane*4);
    float t, ss = 0.f, sd = 0.f;
    t = tanhf(v.x); ss += t*ws.x; sd += t*wd.x;
    t = tanhf(v.y); ss += t*ws.y; sd += t*wd.y;
    t = tanhf(v.z); ss += t*ws.z; sd += t*wd.z;
    t = tanhf(v.w); ss += t*ws.w; sd += t*wd.w;
    #pragma unroll
    for (int o = 16; o > 0; o >>= 1) {
        ss += __shfl_xor_sync(0xffffffffu, ss, o);
        sd += __shfl_xor_sync(0xffffffffu, sd, o);
    }
    if (lane == 0) {
        const int idx = (b*6 + h)*2048 + n;
        g_src[idx] = ss; g_dst[idx] = sd;
    }
}

// =========================================================================
// Kernel 3: M[b,h,i] = leaky(src[i] + max_j dst[j]). One block per (b,h).
// =========================================================================
__global__ __launch_bounds__(256) void rowmax_kernel()
{
    __shared__ float red[256];
    const int bh = blockIdx.x, tid = threadIdx.x;
    float m = -3.0e38f;
    for (int n = tid; n < 2048; n += 256) m = fmaxf(m, g_dst[bh*2048 + n]);
    red[tid] = m; __syncthreads();
    for (int s = 128; s > 0; s >>= 1) {
        if (tid < s) red[tid] = fmaxf(red[tid], red[tid + s]);
        __syncthreads();
    }
    const float mx = red[0];
    for (int n = tid; n < 2048; n += 256) {
        float s = g_src[bh*2048 + n] + mx;
        g_M[bh*2048 + n] = fmaxf(s, 0.2f * s);
    }
}

// =========================================================================
// Kernel 3b: pack adj into transposed bitmask. Warp handles 8 words (MLP=8).
// =========================================================================
__global__ __launch_bounds__(256) void adjpack_kernel(const int* __restrict__ adj)
{
    const int lane = threadIdx.x & 31, wid = threadIdx.x >> 5;
    const int g = blockIdx.x * 8 + wid;           // group id, 0..65535
    const int b = g >> 14;                         // / (2048*8)
    const int rem = g & 16383;
    const int n = rem >> 3;
    const int grp = rem & 7;
    const int* base = adj + ((size_t)(b*2048) + n)*2048 + grp*256 + lane;
    int v[8];
    #pragma unroll
    for (int k = 0; k < 8; k++) v[k] = base[k*32];
    #pragma unroll
    for (int k = 0; k < 8; k++) {
        const unsigned m = __ballot_sync(0xffffffffu, v[k] != 0);
        if (lane == 0) g_adjbits[((size_t)b*64 + grp*8 + k)*2048 + n] = m;
    }
}

// =========================================================================
// Kernel 4: fused attention, HMMA P@V, fp16 2-term split.
// Block = (64 i-rows, h, b), 128 threads = 4 warps, warp covers n32 slice.
// P built fp32 (scaled x256, softmax-invariant) -> split fp16 hi/lo in smem;
// V single fp16 staged via cp.async from g_Vf16.
// Smem map (bytes):
//   V: 2 x (32 rows x 272B)       = 17408   @ 0
//   P: 2 x (hi 64x80 | lo 64x80)  = 20480   @ 17408
//   sDst 2048f                    =  8192   @ 37888
//   sSrc @46080  sM @46336  sLinv @46592  lpart @46848..47360
// =========================================================================
#define ATTN_SMEM_BYTES 47360

__global__ __launch_bounds__(128) void attn_kernel(
    const float* __restrict__ feat_in,
    const float* __restrict__ bias, float* __restrict__ out)
{
    extern __shared__ __align__(16) char dynsm[];
    const unsigned smBase = smem_u32(dynsm);
    const unsigned Vb0 = smBase;
    const unsigned Pb0 = smBase + 17408u;
    float* sDst  = (float*)(dynsm + 37888);
    float* sSrc  = (float*)(dynsm + 46080);
    float* sM    = (float*)(dynsm + 46336);
    float* sLinv = (float*)(dynsm + 46592);
    float* lpart = (float*)(dynsm + 46848);

    const int tid = threadIdx.x;
    const int b = blockIdx.z, h = blockIdx.y;
    const int i0 = blockIdx.x * 64;
    const int bh = b*6 + h;
    const int lane = tid & 31, wid = tid >> 5;

    for (int t = tid; t < 2048; t += 128) sDst[t] = g_dst[bh*2048 + t];
    if (tid < 64) {
        sSrc[tid] = g_src[bh*2048 + i0 + tid];
        sM[tid]   = g_M[bh*2048 + i0 + tid];
    }
    __syncthreads();

    const int il = tid & 63, jh = tid >> 6;        // P-build role
    const float srcv = sSrc[il], Mv = sM[il];
    float psum = 0.f;

    const unsigned* abT = g_adjbits + (size_t)b*64*2048 + (i0 + il);
    const size_t vRowBase = (size_t)(b*2048)*768 + h*128;

    // ldmatrix lane offsets
    const int grp = lane >> 3, l7 = lane & 7;
    const unsigned aOff = (unsigned)(((grp & 1) * 8 + l7) * 80 + (grp >> 1) * 16);
    const unsigned vOff = (unsigned)(((grp & 1) * 8 + l7) * 272 + (grp >> 1) * 16);
    const unsigned nW = (unsigned)(wid * 32 * 2);  // warp's n-slice byte offset

    float acc[4][4][4];
    #pragma unroll
    for (int mi = 0; mi < 4; mi++)
        #pragma unroll
        for (int ni = 0; ni < 4; ni++)
            #pragma unroll
            for (int q = 0; q < 4; q++) acc[mi][ni][q] = 0.f;

    // ---- stage V tile (single fp16) for j-tile jt into buffer buf ----
    auto stageV = [&](int jt, int buf) {
        const unsigned vb = Vb0 + (unsigned)buf * 8704u;
        const int j0 = jt * 32;
        #pragma unroll
        for (int rep = 0; rep < 4; rep++) {
            const int u = rep * 128 + tid;          // 0..511
            const int row = u >> 4, c16 = u & 15;
            const __half* src = g_Vf16 + vRowBase + (size_t)(j0 + row) * 768 + c16 * 8;
            CP_ASYNC16(vb + (unsigned)(row * 272 + c16 * 16), (const char*)src);
        }
        CP_COMMIT();
    };

    // ---- build P (fp32 exp x256, fp16 hi/lo split) for tile jt into buf ----
    auto buildP = [&](int jt, int buf) {
        const int j0 = jt * 32;
        const unsigned am = abT[jt*2048];
        __half2* Ph = (__half2*)(dynsm + 17408 + buf * 10240 + il * 80);
        __half2* Pl = (__half2*)(dynsm + 17408 + buf * 10240 + 5120 + il * 80);
        #pragma unroll
        for (int q = 0; q < 8; q++) {
            const int jb = jh*16 + q*2;
            float s0 = srcv + sDst[j0 + jb + 0]; s0 = fmaxf(s0, 0.2f*s0);
            float s1 = srcv + sDst[j0 + jb + 1]; s1 = fmaxf(s1, 0.2f*s1);
            float p0 = ((am >> (jb+0)) & 1u) ? 256.0f * __expf(s0 - Mv) : 0.f;
            float p1 = ((am >> (jb+1)) & 1u) ? 256.0f * __expf(s1 - Mv) : 0.f;
            psum += p0 + p1;
            const __half h0 = __float2half_rn(p0), h1 = __float2half_rn(p1);
            Ph[jb >> 1] = __halves2half2(h0, h1);
            Pl[jb >> 1] = __halves2half2(__float2half_rn(p0 - __half2float(h0)),
                                         __float2half_rn(p1 - __half2float(h1)));
        }
    };

    stageV(0, 0);
    buildP(0, 0);
    CP_WAIT0();
    __syncthreads();

    for (int jt = 0; jt < 64; jt++) {
        const int cur = jt & 1;

        if (jt < 63) {
            stageV(jt + 1, cur ^ 1);
            buildP(jt + 1, cur ^ 1);
        }

        const unsigned vb = Vb0 + (unsigned)cur * 8704u;
        const unsigned pb = Pb0 + (unsigned)cur * 10240u;

        #pragma unroll
        for (int ks = 0; ks < 2; ks++) {
            const unsigned vk = vb + (unsigned)(ks * 16 * 272) + vOff + nW;
            unsigned vh0[4], vh1[4];
            LDMX4T(vh0[0], vh0[1], vh0[2], vh0[3], vk);
            LDMX4T(vh1[0], vh1[1], vh1[2], vh1[3], vk + 32u);
            #pragma unroll
            for (int mi = 0; mi < 4; mi++) {
                const unsigned pa = pb + (unsigned)(mi * 16 * 80 + ks * 32) + aOff;
                unsigned ph[4], pl[4];
                LDMX4(ph[0], ph[1], ph[2], ph[3], pa);
                LDMX4(pl[0], pl[1], pl[2], pl[3], pa + 5120u);
                MMAH(acc[mi][0], ph[0], ph[1], ph[2], ph[3], vh0[0], vh0[1]);
                MMAH(acc[mi][1], ph[0], ph[1], ph[2], ph[3], vh0[2], vh0[3]);
                MMAH(acc[mi][2], ph[0], ph[1], ph[2], ph[3], vh1[0], vh1[1]);
                MMAH(acc[mi][3], ph[0], ph[1], ph[2], ph[3], vh1[2], vh1[3]);
                MMAH(acc[mi][0], pl[0], pl[1], pl[2], pl[3], vh0[0], vh0[1]);
                MMAH(acc[mi][1], pl[0], pl[1], pl[2], pl[3], vh0[2], vh0[3]);
                MMAH(acc[mi][2], pl[0], pl[1], pl[2], pl[3], vh1[0], vh1[1]);
                MMAH(acc[mi][3], pl[0], pl[1], pl[2], pl[3], vh1[2], vh1[3]);
            }
        }

        if (jt < 63) CP_WAIT0();
        __syncthreads();
    }

    // softmax denominators (x256 scale cancels: numerator carries it too)
    lpart[jh*64 + il] = psum;
    __syncthreads();
    if (tid < 64) sLinv[tid] = 1.0f / (lpart[tid] + lpart[64 + tid]);
    __syncthreads();

    // epilogue: /l + bias, ELU, gated residual
    const int rL = lane >> 2, cL = (lane & 3) * 2;
    #pragma unroll
    for (int mi = 0; mi < 4; mi++) {
        const float linv0 = sLinv[mi*16 + rL];
        const float linv1 = sLinv[mi*16 + rL + 8];
        #pragma unroll
        for (int ni = 0; ni < 4; ni++) {
            const int cb = wid*32 + ni*8 + cL;       // 0..127 within head
            const int col = h*128 + cb;
            const float b0 = bias[cb], b1 = bias[cb + 1];
            #pragma unroll
            for (int half = 0; half < 2; half++) {
                const int nrow = i0 + mi*16 + rL + half*8;
                const float linv = half ? linv1 : linv0;
                const size_t base = ((size_t)(b*2048) + nrow)*768 + col;
                const float2 x = *(const float2*)(feat_in + base);
                const float2 g = *(const float2*)(g_gate + base);
                float fo0 = acc[mi][ni][half*2+0]*linv + b0;
                float fo1 = acc[mi][ni][half*2+1]*linv + b1;
                const float e0 = (fo0 > 0.f) ? fo0 : expm1f(fo0);
                const float e1 = (fo1 > 0.f) ? fo1 : expm1f(fo1);
                *(float2*)(out + base) =
                    make_float2(x.x + g.x*(e0 - x.x), x.y + g.y*(e1 - x.y));
            }
        }
    }
}

extern "C" void kernel_launch(void* const* d_in, const int* in_sizes, int n_in,
                              void* d_out, int out_size) {
    (void)in_sizes; (void)n_in; (void)out_size;
    const float* feat_in = (const float*)d_in[0];
    const int*   adj     = (const int*)d_in[1];
    const float* W       = (const float*)d_in[2];
    const float* bvec    = (const float*)d_in[3];
    const float* w_src   = (const float*)d_in[4];
    const float* w_dst   = (const float*)d_in[5];
    const float* H_w     = (const float*)d_in[6];
    const float* H_b     = (const float*)d_in[7];
    float* out = (float*)d_out;

    cudaFuncSetAttribute(attn_kernel,
                         cudaFuncAttributeMaxDynamicSharedMemorySize, ATTN_SMEM_BYTES);
    cudaFuncSetAttribute(proj_mma,
                         cudaFuncAttributeMaxDynamicSharedMemorySize, PROJ_SMEM_BYTES);

    splitX_kernel<<<6144, 256>>>(feat_in);
    buildB_kernel<<<4608, 256>>>(W, H_w);
    proj_mma<<<dim3(12, 64), 256, PROJ_SMEM_BYTES>>>(H_b);
    adjpack_kernel<<<8192, 256>>>(adj);
    srcdst_kernel<<<6144, 256>>>(w_src, w_dst);
    rowmax_kernel<<<24, 256>>>();
    attn_kernel<<<dim3(32, 6, 4), 128, ATTN_SMEM_BYTES>>>(feat_in, bvec, out);
}

// round 16
// speedup vs baseline: 4.1541x; 1.2386x over previous
#include <cuda_runtime.h>
#include <cuda_fp16.h>
#include <math.h>

typedef unsigned long long ull;

#define Bb 4
#define Nn 2048
#define Dd 768
#define Hh 6
#define Do_ 128

__device__ __align__(16) float g_h[Bb*Nn*Dd];     // per-head projected features, col = h*128+o
__device__ __align__(16) float g_gate[Bb*Nn*Dd];  // sigmoid gate
__device__ float g_src[Bb*Hh*Nn];
__device__ float g_dst[Bb*Hh*Nn];
__device__ float g_M[Bb*Hh*Nn];                   // leaky(src_i + max_j dst_j)
__device__ unsigned g_adjbits[Bb*64*Nn];          // transposed bitmask: [b][word(j/32)][n]

// fp16 operands for the MMA GEMMs
__device__ __align__(16) __half g_Xh[Bb*Nn*Dd];
__device__ __align__(16) __half g_Bh[1536*Dd];    // B[c][i]: c<768 -> W[h][i][o], else H_w row
__device__ __align__(16) __half g_Vf16[Bb*Nn*Dd]; // fp16 copy of g_h (attention V operand)

__device__ __forceinline__ float sigm(float x) { return 1.0f / (1.0f + __expf(-x)); }

#define CP_ASYNC16(dst_u32, src_ptr) \
    asm volatile("cp.async.cg.shared.global [%0], [%1], 16;" :: "r"(dst_u32), "l"(src_ptr))
#define CP_COMMIT()  asm volatile("cp.async.commit_group;" ::: "memory")
#define CP_WAIT0()   asm volatile("cp.async.wait_group 0;" ::: "memory")
#define CP_WAIT1()   asm volatile("cp.async.wait_group 1;" ::: "memory")

__device__ __forceinline__ unsigned smem_u32(const void* p) {
    return (unsigned)__cvta_generic_to_shared(p);
}

#define LDMX4(r0, r1, r2, r3, addr) \
    asm volatile("ldmatrix.sync.aligned.m8n8.x4.shared.b16 {%0,%1,%2,%3}, [%4];" \
        : "=r"(r0), "=r"(r1), "=r"(r2), "=r"(r3) : "r"(addr))
#define LDMX4T(r0, r1, r2, r3, addr) \
    asm volatile("ldmatrix.sync.aligned.m8n8.x4.trans.shared.b16 {%0,%1,%2,%3}, [%4];" \
        : "=r"(r0), "=r"(r1), "=r"(r2), "=r"(r3) : "r"(addr))

#define MMAH(d, a0, a1, a2, a3, b0, b1) \
    asm volatile("mma.sync.aligned.m16n8k16.row.col.f32.f16.f16.f32 " \
        "{%0,%1,%2,%3}, {%4,%5,%6,%7}, {%8,%9}, {%0,%1,%2,%3};" \
        : "+f"((d)[0]), "+f"((d)[1]), "+f"((d)[2]), "+f"((d)[3]) \
        : "r"(a0), "r"(a1), "r"(a2), "r"(a3), "r"(b0), "r"(b1))

// =========================================================================
// Prep 1: convert X to fp16. 4 floats per thread.
// =========================================================================
__global__ __launch_bounds__(256) void cvtX_kernel(const float* __restrict__ X)
{
    const int t = blockIdx.x * 256 + threadIdx.x;       // 0..1572863
    const float4 v = ((const float4*)X)[t];
    __half2* Hi = (__half2*)g_Xh;
    Hi[t*2]   = __floats2half2_rn(v.x, v.y);
    Hi[t*2+1] = __floats2half2_rn(v.z, v.w);
}

// =========================================================================
// Prep 2: build concatenated B [1536 x 768] K-major, fp16.
// c<768: B[c][i] = W[h=c>>7][i][o=c&127]; c>=768: B[c][i] = H_w[c-768][i].
// =========================================================================
__global__ __launch_bounds__(256) void buildB_kernel(
    const float* __restrict__ W, const float* __restrict__ Hw)
{
    const int t = blockIdx.x * 256 + threadIdx.x;       // 0..1179647
    const int c = t / 768, i = t - c * 768;
    float v;
    if (c < 768) v = W[(((size_t)(c >> 7) * 768 + i) * 128) + (c & 127)];
    else         v = Hw[(size_t)(c - 768) * 768 + i];
    g_Bh[t] = __float2half_rn(v);
}

// =========================================================================
// Kernel 1: fp16 GEMM via ldmatrix + mma.sync (HMMA).
// C[8192,1536] = Xh*Bh^T; BM=128 BN=128 BK=32, 256 thr, warp 32x64.
// Smem rows 64B data padded to 80B (bank stride 5 mod 8, conflict-free).
// Stage = [Xh|Bh] x 128 rows x 80B = 20480B; 2 stages.
// Epilogue writes g_h fp32 + fp16 g_Vf16 (V operand for attention).
// =========================================================================
#define PROJ_SMEM_BYTES (40960 + 1024)

__global__ __launch_bounds__(256, 2) void proj_mma(const float* __restrict__ Hb)
{
    extern __shared__ __align__(16) char dynsm[];

    const int tid  = threadIdx.x;
    const int wid  = tid >> 5, lane = tid & 31;
    const int cBase = blockIdx.x * 128;     // 0..1408
    const int m0    = blockIdx.y * 128;

    const unsigned dynBase = (smem_u32(dynsm) + 1023u) & ~1023u;

    const int warpM = (wid & 3) * 32;       // 4 warps over M
    const int warpN = (wid >> 2) * 64;      // 2 warps over N

    const __half* baseSrc[2] = {
        g_Xh + (size_t)m0 * 768, g_Bh + (size_t)cBase * 768 };

    auto stage = [&](int kc, int s) {
        const unsigned sb = dynBase + (unsigned)s * 20480u;
        #pragma unroll
        for (int rep = 0; rep < 4; rep++) {
            const int u = rep * 256 + tid;          // 0..1023
            const int T = u >> 9;
            const int rc = u & 511;
            const int row = rc >> 2, c16 = rc & 3;
            CP_ASYNC16(sb + (unsigned)(T * 10240 + row * 80 + c16 * 16),
                       (const char*)(baseSrc[T] + (size_t)row * 768 + kc * 32 + c16 * 8));
        }
        CP_COMMIT();
    };

    const int grp = lane >> 3, l7 = lane & 7;
    const unsigned aLane = (unsigned)(((grp & 1) * 8 + l7) * 80 + (grp >> 1) * 16);
    const unsigned bLane = (unsigned)(((grp >> 1) * 8 + l7) * 80 + (grp & 1) * 16);

    float acc[2][8][4];
    #pragma unroll
    for (int mi = 0; mi < 2; mi++)
        #pragma unroll
        for (int ni = 0; ni < 8; ni++)
            #pragma unroll
            for (int q = 0; q < 4; q++) acc[mi][ni][q] = 0.f;

    stage(0, 0);
    stage(1, 1);

    for (int kc = 0; kc < 24; kc++) {
        const int s = kc & 1;
        CP_WAIT1();
        __syncthreads();

        const unsigned sb   = dynBase + (unsigned)s * 20480u;
        const unsigned aB = sb          + (unsigned)(warpM * 80) + aLane;
        const unsigned bB = sb + 10240u + (unsigned)(warpN * 80) + bLane;

        #pragma unroll
        for (int ks = 0; ks < 2; ks++) {
            const unsigned ko = (unsigned)(ks * 32);
            unsigned ah[2][4];
            LDMX4(ah[0][0], ah[0][1], ah[0][2], ah[0][3], aB + ko);
            LDMX4(ah[1][0], ah[1][1], ah[1][2], ah[1][3], aB + ko + 16u*80u);
            #pragma unroll
            for (int nb = 0; nb < 4; nb++) {
                unsigned bh0, bh1, bh2, bh3;
                LDMX4(bh0, bh1, bh2, bh3, bB + ko + (unsigned)(nb * 16 * 80));
                #pragma unroll
                for (int mi = 0; mi < 2; mi++) {
                    MMAH(acc[mi][nb*2+0], ah[mi][0], ah[mi][1], ah[mi][2], ah[mi][3], bh0, bh1);
                    MMAH(acc[mi][nb*2+1], ah[mi][0], ah[mi][1], ah[mi][2], ah[mi][3], bh2, bh3);
                }
            }
        }
        __syncthreads();
        if (kc + 2 < 24) stage(kc + 2, s);
    }

    const bool isGate = (cBase >= 768);
    const int rBase = m0 + warpM + (lane >> 2);
    const int cLane = 2 * (lane & 3);
    #pragma unroll
    for (int mi = 0; mi < 2; mi++) {
        #pragma unroll
        for (int ni = 0; ni < 8; ni++) {
            const int col = cBase + warpN + ni * 8 + cLane;
            const int r0 = rBase + mi * 16;
            if (!isGate) {
                const float v0 = acc[mi][ni][0], v1 = acc[mi][ni][1];
                const float v2 = acc[mi][ni][2], v3 = acc[mi][ni][3];
                *(float2*)(g_h + (size_t)r0 * 768 + col)       = make_float2(v0, v1);
                *(float2*)(g_h + (size_t)(r0 + 8) * 768 + col) = make_float2(v2, v3);
                *(__half2*)(g_Vf16 + (size_t)r0 * 768 + col)       = __floats2half2_rn(v0, v1);
                *(__half2*)(g_Vf16 + (size_t)(r0 + 8) * 768 + col) = __floats2half2_rn(v2, v3);
            } else {
                const int cg = col - 768;
                const float hb0 = Hb[cg], hb1 = Hb[cg + 1];
                *(float2*)(g_gate + (size_t)r0 * 768 + cg) =
                    make_float2(sigm(acc[mi][ni][0] + hb0), sigm(acc[mi][ni][1] + hb1));
                *(float2*)(g_gate + (size_t)(r0 + 8) * 768 + cg) =
                    make_float2(sigm(acc[mi][ni][2] + hb0), sigm(acc[mi][ni][3] + hb1));
            }
        }
    }
}

// =========================================================================
// Kernel 2: src/dst = <tanh(h[b,h,n,:]), w_src/w_dst>. One warp per row.
// =========================================================================
__global__ __launch_bounds__(256) void srcdst_kernel(
    const float* __restrict__ wsrc, const float* __restrict__ wdst)
{
    const int tid = threadIdx.x, lane = tid & 31, wid = tid >> 5;
    const int gid = blockIdx.x * 8 + wid;          // 0..49151
    const int b = gid / 12288;
    const int r = gid - b * 12288;
    const int h = r >> 11;
    const int n = r & 2047;

    const float4 v  = *(const float4*)(g_h + (size_t)(b*2048 + n)*768 + h*128 + lane*4);
    const float4 ws = *(const float4*)(wsrc + h*128 + lane*4);
    const float4 wd = *(const float4*)(wdst + h*128 + lane*4);
    float t, ss = 0.f, sd = 0.f;
    t = tanhf(v.x); ss += t*ws.x; sd += t*wd.x;
    t = tanhf(v.y); ss += t*ws.y; sd += t*wd.y;
    t = tanhf(v.z); ss += t*ws.z; sd += t*wd.z;
    t = tanhf(v.w); ss += t*ws.w; sd += t*wd.w;
    #pragma unroll
    for (int o = 16; o > 0; o >>= 1) {
        ss += __shfl_xor_sync(0xffffffffu, ss, o);
        sd += __shfl_xor_sync(0xffffffffu, sd, o);
    }
    if (lane == 0) {
        const int idx = (b*6 + h)*2048 + n;
        g_src[idx] = ss; g_dst[idx] = sd;
    }
}

// =========================================================================
// Kernel 3: M[b,h,i] = leaky(src[i] + max_j dst[j]). One block per (b,h).
// =========================================================================
__global__ __launch_bounds__(256) void rowmax_kernel()
{
    __shared__ float red[256];
    const int bh = blockIdx.x, tid = threadIdx.x;
    float m = -3.0e38f;
    for (int n = tid; n < 2048; n += 256) m = fmaxf(m, g_dst[bh*2048 + n]);
    red[tid] = m; __syncthreads();
    for (int s = 128; s > 0; s >>= 1) {
        if (tid < s) red[tid] = fmaxf(red[tid], red[tid + s]);
        __syncthreads();
    }
    const float mx = red[0];
    for (int n = tid; n < 2048; n += 256) {
        float s = g_src[bh*2048 + n] + mx;
        g_M[bh*2048 + n] = fmaxf(s, 0.2f * s);
    }
}

// =========================================================================
// Kernel 3b: pack adj into transposed bitmask. Warp handles 8 words (MLP=8).
// =========================================================================
__global__ __launch_bounds__(256) void adjpack_kernel(const int* __restrict__ adj)
{
    const int lane = threadIdx.x & 31, wid = threadIdx.x >> 5;
    const int g = blockIdx.x * 8 + wid;           // group id, 0..65535
    const int b = g >> 14;                         // / (2048*8)
    const int rem = g & 16383;
    const int n = rem >> 3;
    const int grp = rem & 7;
    const int* base = adj + ((size_t)(b*2048) + n)*2048 + grp*256 + lane;
    int v[8];
    #pragma unroll
    for (int k = 0; k < 8; k++) v[k] = base[k*32];
    #pragma unroll
    for (int k = 0; k < 8; k++) {
        const unsigned m = __ballot_sync(0xffffffffu, v[k] != 0);
        if (lane == 0) g_adjbits[((size_t)b*64 + grp*8 + k)*2048 + n] = m;
    }
}

// =========================================================================
// Kernel 4: fused attention, HMMA P@V, single fp16 P and V.
// Block = (64 i-rows, h, b), 128 threads = 4 warps, warp covers n32 slice.
// P built fp32 (scaled x256, softmax-invariant) -> fp16 in smem; V fp16
// staged via cp.async from g_Vf16. l accumulated in exact fp32.
// Smem map (bytes):
//   V: 2 x (32 rows x 272B) = 17408  @ 0
//   P: 2 x (64 rows x 80B)  = 10240  @ 17408
//   sDst 2048f              =  8192  @ 27648
//   sSrc @35840  sM @36096  sLinv @36352  lpart @36608..37120
// =========================================================================
#define ATTN_SMEM_BYTES 37120

__global__ __launch_bounds__(128) void attn_kernel(
    const float* __restrict__ feat_in,
    const float* __restrict__ bias, float* __restrict__ out)
{
    extern __shared__ __align__(16) char dynsm[];
    const unsigned smBase = smem_u32(dynsm);
    const unsigned Vb0 = smBase;
    const unsigned Pb0 = smBase + 17408u;
    float* sDst  = (float*)(dynsm + 27648);
    float* sSrc  = (float*)(dynsm + 35840);
    float* sM    = (float*)(dynsm + 36096);
    float* sLinv = (float*)(dynsm + 36352);
    float* lpart = (float*)(dynsm + 36608);

    const int tid = threadIdx.x;
    const int b = blockIdx.z, h = blockIdx.y;
    const int i0 = blockIdx.x * 64;
    const int bh = b*6 + h;
    const int lane = tid & 31, wid = tid >> 5;

    for (int t = tid; t < 2048; t += 128) sDst[t] = g_dst[bh*2048 + t];
    if (tid < 64) {
        sSrc[tid] = g_src[bh*2048 + i0 + tid];
        sM[tid]   = g_M[bh*2048 + i0 + tid];
    }
    __syncthreads();

    const int il = tid & 63, jh = tid >> 6;        // P-build role
    const float srcv = sSrc[il], Mv = sM[il];
    float psum = 0.f;

    const unsigned* abT = g_adjbits + (size_t)b*64*2048 + (i0 + il);
    const size_t vRowBase = (size_t)(b*2048)*768 + h*128;

    // ldmatrix lane offsets
    const int grp = lane >> 3, l7 = lane & 7;
    const unsigned aOff = (unsigned)(((grp & 1) * 8 + l7) * 80 + (grp >> 1) * 16);
    const unsigned vOff = (unsigned)(((grp & 1) * 8 + l7) * 272 + (grp >> 1) * 16);
    const unsigned nW = (unsigned)(wid * 32 * 2);  // warp's n-slice byte offset

    float acc[4][4][4];
    #pragma unroll
    for (int mi = 0; mi < 4; mi++)
        #pragma unroll
        for (int ni = 0; ni < 4; ni++)
            #pragma unroll
            for (int q = 0; q < 4; q++) acc[mi][ni][q] = 0.f;

    // ---- stage V tile (fp16) for j-tile jt into buffer buf ----
    auto stageV = [&](int jt, int buf) {
        const unsigned vb = Vb0 + (unsigned)buf * 8704u;
        const int j0 = jt * 32;
        #pragma unroll
        for (int rep = 0; rep < 4; rep++) {
            const int u = rep * 128 + tid;          // 0..511
            const int row = u >> 4, c16 = u & 15;
            const __half* src = g_Vf16 + vRowBase + (size_t)(j0 + row) * 768 + c16 * 8;
            CP_ASYNC16(vb + (unsigned)(row * 272 + c16 * 16), (const char*)src);
        }
        CP_COMMIT();
    };

    // ---- build P (fp32 exp x256 -> fp16) for tile jt into buf ----
    auto buildP = [&](int jt, int buf) {
        const int j0 = jt * 32;
        const unsigned am = abT[jt*2048];
        __half2* Ph = (__half2*)(dynsm + 17408 + buf * 5120 + il * 80);
        #pragma unroll
        for (int q = 0; q < 8; q++) {
            const int jb = jh*16 + q*2;
            float s0 = srcv + sDst[j0 + jb + 0]; s0 = fmaxf(s0, 0.2f*s0);
            float s1 = srcv + sDst[j0 + jb + 1]; s1 = fmaxf(s1, 0.2f*s1);
            float p0 = ((am >> (jb+0)) & 1u) ? 256.0f * __expf(s0 - Mv) : 0.f;
            float p1 = ((am >> (jb+1)) & 1u) ? 256.0f * __expf(s1 - Mv) : 0.f;
            psum += p0 + p1;
            Ph[jb >> 1] = __floats2half2_rn(p0, p1);
        }
    };

    stageV(0, 0);
    buildP(0, 0);
    CP_WAIT0();
    __syncthreads();

    for (int jt = 0; jt < 64; jt++) {
        const int cur = jt & 1;

        if (jt < 63) {
            stageV(jt + 1, cur ^ 1);
            buildP(jt + 1, cur ^ 1);
        }

        const unsigned vb = Vb0 + (unsigned)cur * 8704u;
        const unsigned pb = Pb0 + (unsigned)cur * 5120u;

        #pragma unroll
        for (int ks = 0; ks < 2; ks++) {
            const unsigned vk = vb + (unsigned)(ks * 16 * 272) + vOff + nW;
            unsigned vh0[4], vh1[4];
            LDMX4T(vh0[0], vh0[1], vh0[2], vh0[3], vk);
            LDMX4T(vh1[0], vh1[1], vh1[2], vh1[3], vk + 32u);
            #pragma unroll
            for (int mi = 0; mi < 4; mi++) {
                const unsigned pa = pb + (unsigned)(mi * 16 * 80 + ks * 32) + aOff;
                unsigned ph[4];
                LDMX4(ph[0], ph[1], ph[2], ph[3], pa);
                MMAH(acc[mi][0], ph[0], ph[1], ph[2], ph[3], vh0[0], vh0[1]);
                MMAH(acc[mi][1], ph[0], ph[1], ph[2], ph[3], vh0[2], vh0[3]);
                MMAH(acc[mi][2], ph[0], ph[1], ph[2], ph[3], vh1[0], vh1[1]);
                MMAH(acc[mi][3], ph[0], ph[1], ph[2], ph[3], vh1[2], vh1[3]);
            }
        }

        if (jt < 63) CP_WAIT0();
        __syncthreads();
    }

    // softmax denominators (x256 scale cancels: numerator carries it too)
    lpart[jh*64 + il] = psum;
    __syncthreads();
    if (tid < 64) sLinv[tid] = 1.0f / (lpart[tid] + lpart[64 + tid]);
    __syncthreads();

    // epilogue: /l + bias, ELU, gated residual
    const int rL = lane >> 2, cL = (lane & 3) * 2;
    #pragma unroll
    for (int mi = 0; mi < 4; mi++) {
        const float linv0 = sLinv[mi*16 + rL];
        const float linv1 = sLinv[mi*16 + rL + 8];
        #pragma unroll
        for (int ni = 0; ni < 4; ni++) {
            const int cb = wid*32 + ni*8 + cL;       // 0..127 within head
            const int col = h*128 + cb;
            const float b0 = bias[cb], b1 = bias[cb + 1];
            #pragma unroll
            for (int half = 0; half < 2; half++) {
                const int nrow = i0 + mi*16 + rL + half*8;
                const float linv = half ? linv1 : linv0;
                const size_t base = ((size_t)(b*2048) + nrow)*768 + col;
                const float2 x = *(const float2*)(feat_in + base);
                const float2 g = *(const float2*)(g_gate + base);
                float fo0 = acc[mi][ni][half*2+0]*linv + b0;
                float fo1 = acc[mi][ni][half*2+1]*linv + b1;
                const float e0 = (fo0 > 0.f) ? fo0 : expm1f(fo0);
                const float e1 = (fo1 > 0.f) ? fo1 : expm1f(fo1);
                *(float2*)(out + base) =
                    make_float2(x.x + g.x*(e0 - x.x), x.y + g.y*(e1 - x.y));
            }
        }
    }
}

extern "C" void kernel_launch(void* const* d_in, const int* in_sizes, int n_in,
                              void* d_out, int out_size) {
    (void)in_sizes; (void)n_in; (void)out_size;
    const float* feat_in = (const float*)d_in[0];
    const int*   adj     = (const int*)d_in[1];
    const float* W       = (const float*)d_in[2];
    const float* bvec    = (const float*)d_in[3];
    const float* w_src   = (const float*)d_in[4];
    const float* w_dst   = (const float*)d_in[5];
    const float* H_w     = (const float*)d_in[6];
    const float* H_b     = (const float*)d_in[7];
    float* out = (float*)d_out;

    cudaFuncSetAttribute(attn_kernel,
                         cudaFuncAttributeMaxDynamicSharedMemorySize, ATTN_SMEM_BYTES);
    cudaFuncSetAttribute(proj_mma,
                         cudaFuncAttributeMaxDynamicSharedMemorySize, PROJ_SMEM_BYTES);

    cvtX_kernel<<<6144, 256>>>(feat_in);
    buildB_kernel<<<4608, 256>>>(W, H_w);
    proj_mma<<<dim3(12, 64), 256, PROJ_SMEM_BYTES>>>(H_b);
    adjpack_kernel<<<8192, 256>>>(adj);
    srcdst_kernel<<<6144, 256>>>(w_src, w_dst);
    rowmax_kernel<<<24, 256>>>();
    attn_kernel<<<dim3(32, 6, 4), 128, ATTN_SMEM_BYTES>>>(feat_in, bvec, out);
}

// round 17
// speedup vs baseline: 4.2283x; 1.0179x over previous
#include <cuda_runtime.h>
#include <cuda_fp16.h>
#include <math.h>

typedef unsigned long long ull;

#define Bb 4
#define Nn 2048
#define Dd 768
#define Hh 6
#define Do_ 128

__device__ __align__(16) float g_gate[Bb*Nn*Dd];  // sigmoid gate
__device__ float g_src[Bb*Hh*Nn];
__device__ float g_dst[Bb*Hh*Nn];
__device__ float g_dstmax[Bb*Hh];                 // max_j dst[j] per (b,h)
__device__ unsigned g_adjbits[Bb*64*Nn];          // transposed bitmask: [b][word(j/32)][n]

// fp16 operands for the MMA GEMMs
__device__ __align__(16) __half g_Xh[Bb*Nn*Dd];
__device__ __align__(16) __half g_Bh[1536*Dd];    // B[c][i]: c<768 -> W[h][i][o], else H_w row
__device__ __align__(16) __half g_Vf16[Bb*Nn*Dd]; // fp16 per-head features (attention V operand)

__device__ __forceinline__ float sigm(float x) { return 1.0f / (1.0f + __expf(-x)); }

__device__ __forceinline__ void atomicMaxF(float* a, float v) {
    if (v >= 0.f) atomicMax((int*)a, __float_as_int(v));
    else          atomicMin((unsigned*)a, __float_as_uint(v));
}

#define CP_ASYNC16(dst_u32, src_ptr) \
    asm volatile("cp.async.cg.shared.global [%0], [%1], 16;" :: "r"(dst_u32), "l"(src_ptr))
#define CP_COMMIT()  asm volatile("cp.async.commit_group;" ::: "memory")
#define CP_WAIT0()   asm volatile("cp.async.wait_group 0;" ::: "memory")
#define CP_WAIT1()   asm volatile("cp.async.wait_group 1;" ::: "memory")

__device__ __forceinline__ unsigned smem_u32(const void* p) {
    return (unsigned)__cvta_generic_to_shared(p);
}

#define LDMX4(r0, r1, r2, r3, addr) \
    asm volatile("ldmatrix.sync.aligned.m8n8.x4.shared.b16 {%0,%1,%2,%3}, [%4];" \
        : "=r"(r0), "=r"(r1), "=r"(r2), "=r"(r3) : "r"(addr))
#define LDMX4T(r0, r1, r2, r3, addr) \
    asm volatile("ldmatrix.sync.aligned.m8n8.x4.trans.shared.b16 {%0,%1,%2,%3}, [%4];" \
        : "=r"(r0), "=r"(r1), "=r"(r2), "=r"(r3) : "r"(addr))

#define MMAH(d, a0, a1, a2, a3, b0, b1) \
    asm volatile("mma.sync.aligned.m16n8k16.row.col.f32.f16.f16.f32 " \
        "{%0,%1,%2,%3}, {%4,%5,%6,%7}, {%8,%9}, {%0,%1,%2,%3};" \
        : "+f"((d)[0]), "+f"((d)[1]), "+f"((d)[2]), "+f"((d)[3]) \
        : "r"(a0), "r"(a1), "r"(a2), "r"(a3), "r"(b0), "r"(b1))

// =========================================================================
// Prep 1: convert X to fp16 (+ init g_dstmax). 4 floats per thread.
// =========================================================================
__global__ __launch_bounds__(256) void cvtX_kernel(const float* __restrict__ X)
{
    if (blockIdx.x == 0 && threadIdx.x < Bb*Hh) g_dstmax[threadIdx.x] = -3.0e38f;
    const int t = blockIdx.x * 256 + threadIdx.x;       // 0..1572863
    const float4 v = ((const float4*)X)[t];
    __half2* Hi = (__half2*)g_Xh;
    Hi[t*2]   = __floats2half2_rn(v.x, v.y);
    Hi[t*2+1] = __floats2half2_rn(v.z, v.w);
}

// =========================================================================
// Prep 2: build concatenated B [1536 x 768] K-major, fp16.
// c<768: B[c][i] = W[h=c>>7][i][o=c&127]; c>=768: B[c][i] = H_w[c-768][i].
// =========================================================================
__global__ __launch_bounds__(256) void buildB_kernel(
    const float* __restrict__ W, const float* __restrict__ Hw)
{
    const int t = blockIdx.x * 256 + threadIdx.x;       // 0..1179647
    const int c = t / 768, i = t - c * 768;
    float v;
    if (c < 768) v = W[(((size_t)(c >> 7) * 768 + i) * 128) + (c & 127)];
    else         v = Hw[(size_t)(c - 768) * 768 + i];
    g_Bh[t] = __float2half_rn(v);
}

// =========================================================================
// Kernel 1: fp16 GEMM via ldmatrix + mma.sync (HMMA), fused epilogues.
// C[8192,1536] = Xh*Bh^T; BM=128 BN=128 BK=32, 256 thr, warp 32x64.
// Head blocks (cBase<768): write fp16 V; fused tanh-dot src/dst reduction
// (whole head's 128 cols live in this block) + per-block dstmax atomic.
// Gate blocks: sigmoid+bias -> g_gate.
// =========================================================================
#define PROJ_SMEM_BYTES (40960 + 1024)

__global__ __launch_bounds__(256, 2) void proj_mma(
    const float* __restrict__ Hb,
    const float* __restrict__ wsrc, const float* __restrict__ wdst)
{
    extern __shared__ __align__(16) char dynsm[];
    __shared__ float s_part[2][2][128];   // [src/dst][warpN][row]
    __shared__ float s_redmax[8];

    const int tid  = threadIdx.x;
    const int wid  = tid >> 5, lane = tid & 31;
    const int cBase = blockIdx.x * 128;     // 0..1408
    const int m0    = blockIdx.y * 128;

    const unsigned dynBase = (smem_u32(dynsm) + 1023u) & ~1023u;

    const int warpM = (wid & 3) * 32;       // 4 warps over M
    const int warpN = (wid >> 2) * 64;      // 2 warps over N
    const int wn = wid >> 2;

    const __half* baseSrc[2] = {
        g_Xh + (size_t)m0 * 768, g_Bh + (size_t)cBase * 768 };

    auto stage = [&](int kc, int s) {
        const unsigned sb = dynBase + (unsigned)s * 20480u;
        #pragma unroll
        for (int rep = 0; rep < 4; rep++) {
            const int u = rep * 256 + tid;          // 0..1023
            const int T = u >> 9;
            const int rc = u & 511;
            const int row = rc >> 2, c16 = rc & 3;
            CP_ASYNC16(sb + (unsigned)(T * 10240 + row * 80 + c16 * 16),
                       (const char*)(baseSrc[T] + (size_t)row * 768 + kc * 32 + c16 * 8));
        }
        CP_COMMIT();
    };

    const int grp = lane >> 3, l7 = lane & 7;
    const unsigned aLane = (unsigned)(((grp & 1) * 8 + l7) * 80 + (grp >> 1) * 16);
    const unsigned bLane = (unsigned)(((grp >> 1) * 8 + l7) * 80 + (grp & 1) * 16);

    float acc[2][8][4];
    #pragma unroll
    for (int mi = 0; mi < 2; mi++)
        #pragma unroll
        for (int ni = 0; ni < 8; ni++)
            #pragma unroll
            for (int q = 0; q < 4; q++) acc[mi][ni][q] = 0.f;

    stage(0, 0);
    stage(1, 1);

    for (int kc = 0; kc < 24; kc++) {
        const int s = kc & 1;
        CP_WAIT1();
        __syncthreads();

        const unsigned sb   = dynBase + (unsigned)s * 20480u;
        const unsigned aB = sb          + (unsigned)(warpM * 80) + aLane;
        const unsigned bB = sb + 10240u + (unsigned)(warpN * 80) + bLane;

        #pragma unroll
        for (int ks = 0; ks < 2; ks++) {
            const unsigned ko = (unsigned)(ks * 32);
            unsigned ah[2][4];
            LDMX4(ah[0][0], ah[0][1], ah[0][2], ah[0][3], aB + ko);
            LDMX4(ah[1][0], ah[1][1], ah[1][2], ah[1][3], aB + ko + 16u*80u);
            #pragma unroll
            for (int nb = 0; nb < 4; nb++) {
                unsigned bh0, bh1, bh2, bh3;
                LDMX4(bh0, bh1, bh2, bh3, bB + ko + (unsigned)(nb * 16 * 80));
                #pragma unroll
                for (int mi = 0; mi < 2; mi++) {
                    MMAH(acc[mi][nb*2+0], ah[mi][0], ah[mi][1], ah[mi][2], ah[mi][3], bh0, bh1);
                    MMAH(acc[mi][nb*2+1], ah[mi][0], ah[mi][1], ah[mi][2], ah[mi][3], bh2, bh3);
                }
            }
        }
        __syncthreads();
        if (kc + 2 < 24) stage(kc + 2, s);
    }

    const bool isGate = (cBase >= 768);
    const int rBase = m0 + warpM + (lane >> 2);
    const int cLane = 2 * (lane & 3);

    if (!isGate) {
        const int h = cBase >> 7;
        const float* wsp = wsrc + h*128;
        const float* wdp = wdst + h*128;
        float ssr[4] = {0.f,0.f,0.f,0.f};   // rows warpM+rL + {0,8,16,24}
        float sdr[4] = {0.f,0.f,0.f,0.f};
        #pragma unroll
        for (int mi = 0; mi < 2; mi++) {
            #pragma unroll
            for (int ni = 0; ni < 8; ni++) {
                const int col = warpN + ni * 8 + cLane;
                const int r0 = rBase + mi * 16;
                const float v0 = acc[mi][ni][0], v1 = acc[mi][ni][1];
                const float v2 = acc[mi][ni][2], v3 = acc[mi][ni][3];
                *(__half2*)(g_Vf16 + (size_t)r0 * 768 + h*128 + col)       = __floats2half2_rn(v0, v1);
                *(__half2*)(g_Vf16 + (size_t)(r0 + 8) * 768 + h*128 + col) = __floats2half2_rn(v2, v3);
                const float w0s = wsp[col], w1s = wsp[col+1];
                const float w0d = wdp[col], w1d = wdp[col+1];
                float t;
                t = tanhf(v0); ssr[mi*2]   += t*w0s; sdr[mi*2]   += t*w0d;
                t = tanhf(v1); ssr[mi*2]   += t*w1s; sdr[mi*2]   += t*w1d;
                t = tanhf(v2); ssr[mi*2+1] += t*w0s; sdr[mi*2+1] += t*w0d;
                t = tanhf(v3); ssr[mi*2+1] += t*w1s; sdr[mi*2+1] += t*w1d;
            }
        }
        // combine 4 lanes of each row group (cols), then 2 N-warps via smem
        #pragma unroll
        for (int r = 0; r < 4; r++) {
            #pragma unroll
            for (int o = 1; o <= 2; o <<= 1) {
                ssr[r] += __shfl_xor_sync(0xffffffffu, ssr[r], o);
                sdr[r] += __shfl_xor_sync(0xffffffffu, sdr[r], o);
            }
        }
        if ((lane & 3) == 0) {
            #pragma unroll
            for (int r = 0; r < 4; r++) {
                const int rowL = warpM + (lane >> 2) + (r & 1) * 8 + (r >> 1) * 16;
                s_part[0][wn][rowL] = ssr[r];
                s_part[1][wn][rowL] = sdr[r];
            }
        }
        __syncthreads();
        const int bb = m0 >> 11;
        const int bh = bb * 6 + h;
        float mval = -3.0e38f;
        if (tid < 128) {
            const int row = tid;
            const float ss = s_part[0][0][row] + s_part[0][1][row];
            const float sd = s_part[1][0][row] + s_part[1][1][row];
            const int n = (m0 + row) & 2047;
            g_src[bh*2048 + n] = ss;
            g_dst[bh*2048 + n] = sd;
            mval = sd;
        }
        #pragma unroll
        for (int o = 16; o > 0; o >>= 1)
            mval = fmaxf(mval, __shfl_xor_sync(0xffffffffu, mval, o));
        if (lane == 0) s_redmax[wid] = mval;
        __syncthreads();
        if (tid == 0) {
            float m2 = s_redmax[0];
            #pragma unroll
            for (int w = 1; w < 8; w++) m2 = fmaxf(m2, s_redmax[w]);
            atomicMaxF(&g_dstmax[bh], m2);
        }
    } else {
        #pragma unroll
        for (int mi = 0; mi < 2; mi++) {
            #pragma unroll
            for (int ni = 0; ni < 8; ni++) {
                const int col = cBase + warpN + ni * 8 + cLane;
                const int r0 = rBase + mi * 16;
                const int cg = col - 768;
                const float hb0 = Hb[cg], hb1 = Hb[cg + 1];
                *(float2*)(g_gate + (size_t)r0 * 768 + cg) =
                    make_float2(sigm(acc[mi][ni][0] + hb0), sigm(acc[mi][ni][1] + hb1));
                *(float2*)(g_gate + (size_t)(r0 + 8) * 768 + cg) =
                    make_float2(sigm(acc[mi][ni][2] + hb0), sigm(acc[mi][ni][3] + hb1));
            }
        }
    }
}

// =========================================================================
// Kernel 3b: pack adj into transposed bitmask. Lane loads int4 -> nibble,
// OR-combine via 3 xor-shuffles; warp covers 128 j of one (b,n).
// =========================================================================
__global__ __launch_bounds__(256) void adjpack_kernel(const int* __restrict__ adj)
{
    const int lane = threadIdx.x & 31, wid = threadIdx.x >> 5;
    const int g = blockIdx.x * 8 + wid;           // 0..131071
    const int b = g >> 15;                         // / (2048*16)
    const int rem = g & 32767;
    const int n = rem >> 4;
    const int grp = rem & 15;
    const int4 v = *(const int4*)(adj + ((size_t)(b*2048) + n)*2048 + grp*128 + lane*4);
    unsigned nib = (unsigned)(v.x != 0) | ((unsigned)(v.y != 0) << 1)
                 | ((unsigned)(v.z != 0) << 2) | ((unsigned)(v.w != 0) << 3);
    unsigned word = nib << (4 * (lane & 7));
    word |= __shfl_xor_sync(0xffffffffu, word, 1);
    word |= __shfl_xor_sync(0xffffffffu, word, 2);
    word |= __shfl_xor_sync(0xffffffffu, word, 4);
    if ((lane & 7) == 0)
        g_adjbits[((size_t)b*64 + grp*4 + (lane >> 3))*2048 + n] = word;
}

// =========================================================================
// Kernel 4: fused attention, HMMA P@V, single fp16 P and V.
// M computed inline from g_src + g_dstmax (leaky monotone bound).
// =========================================================================
#define ATTN_SMEM_BYTES 37120

__global__ __launch_bounds__(128) void attn_kernel(
    const float* __restrict__ feat_in,
    const float* __restrict__ bias, float* __restrict__ out)
{
    extern __shared__ __align__(16) char dynsm[];
    const unsigned smBase = smem_u32(dynsm);
    const unsigned Vb0 = smBase;
    const unsigned Pb0 = smBase + 17408u;
    float* sDst  = (float*)(dynsm + 27648);
    float* sSrc  = (float*)(dynsm + 35840);
    float* sLinv = (float*)(dynsm + 36352);
    float* lpart = (float*)(dynsm + 36608);

    const int tid = threadIdx.x;
    const int b = blockIdx.z, h = blockIdx.y;
    const int i0 = blockIdx.x * 64;
    const int bh = b*6 + h;
    const int lane = tid & 31, wid = tid >> 5;

    for (int t = tid; t < 2048; t += 128) sDst[t] = g_dst[bh*2048 + t];
    if (tid < 64) sSrc[tid] = g_src[bh*2048 + i0 + tid];
    __syncthreads();

    const int il = tid & 63, jh = tid >> 6;        // P-build role
    const float srcv = sSrc[il];
    const float mx = g_dstmax[bh];
    float Mv = srcv + mx; Mv = fmaxf(Mv, 0.2f * Mv);
    float psum = 0.f;

    const unsigned* abT = g_adjbits + (size_t)b*64*2048 + (i0 + il);
    const size_t vRowBase = (size_t)(b*2048)*768 + h*128;

    // ldmatrix lane offsets
    const int grp = lane >> 3, l7 = lane & 7;
    const unsigned aOff = (unsigned)(((grp & 1) * 8 + l7) * 80 + (grp >> 1) * 16);
    const unsigned vOff = (unsigned)(((grp & 1) * 8 + l7) * 272 + (grp >> 1) * 16);
    const unsigned nW = (unsigned)(wid * 32 * 2);  // warp's n-slice byte offset

    float acc[4][4][4];
    #pragma unroll
    for (int mi = 0; mi < 4; mi++)
        #pragma unroll
        for (int ni = 0; ni < 4; ni++)
            #pragma unroll
            for (int q = 0; q < 4; q++) acc[mi][ni][q] = 0.f;

    auto stageV = [&](int jt, int buf) {
        const unsigned vb = Vb0 + (unsigned)buf * 8704u;
        const int j0 = jt * 32;
        #pragma unroll
        for (int rep = 0; rep < 4; rep++) {
            const int u = rep * 128 + tid;          // 0..511
            const int row = u >> 4, c16 = u & 15;
            const __half* src = g_Vf16 + vRowBase + (size_t)(j0 + row) * 768 + c16 * 8;
            CP_ASYNC16(vb + (unsigned)(row * 272 + c16 * 16), (const char*)src);
        }
        CP_COMMIT();
    };

    auto buildP = [&](int jt, int buf) {
        const int j0 = jt * 32;
        const unsigned am = abT[jt*2048];
        __half2* Ph = (__half2*)(dynsm + 17408 + buf * 5120 + il * 80);
        #pragma unroll
        for (int q = 0; q < 8; q++) {
            const int jb = jh*16 + q*2;
            float s0 = srcv + sDst[j0 + jb + 0]; s0 = fmaxf(s0, 0.2f*s0);
            float s1 = srcv + sDst[j0 + jb + 1]; s1 = fmaxf(s1, 0.2f*s1);
            float p0 = ((am >> (jb+0)) & 1u) ? 256.0f * __expf(s0 - Mv) : 0.f;
            float p1 = ((am >> (jb+1)) & 1u) ? 256.0f * __expf(s1 - Mv) : 0.f;
            psum += p0 + p1;
            Ph[jb >> 1] = __floats2half2_rn(p0, p1);
        }
    };

    stageV(0, 0);
    buildP(0, 0);
    CP_WAIT0();
    __syncthreads();

    for (int jt = 0; jt < 64; jt++) {
        const int cur = jt & 1;

        if (jt < 63) {
            stageV(jt + 1, cur ^ 1);
            buildP(jt + 1, cur ^ 1);
        }

        const unsigned vb = Vb0 + (unsigned)cur * 8704u;
        const unsigned pb = Pb0 + (unsigned)cur * 5120u;

        #pragma unroll
        for (int ks = 0; ks < 2; ks++) {
            const unsigned vk = vb + (unsigned)(ks * 16 * 272) + vOff + nW;
            unsigned vh0[4], vh1[4];
            LDMX4T(vh0[0], vh0[1], vh0[2], vh0[3], vk);
            LDMX4T(vh1[0], vh1[1], vh1[2], vh1[3], vk + 32u);
            #pragma unroll
            for (int mi = 0; mi < 4; mi++) {
                const unsigned pa = pb + (unsigned)(mi * 16 * 80 + ks * 32) + aOff;
                unsigned ph[4];
                LDMX4(ph[0], ph[1], ph[2], ph[3], pa);
                MMAH(acc[mi][0], ph[0], ph[1], ph[2], ph[3], vh0[0], vh0[1]);
                MMAH(acc[mi][1], ph[0], ph[1], ph[2], ph[3], vh0[2], vh0[3]);
                MMAH(acc[mi][2], ph[0], ph[1], ph[2], ph[3], vh1[0], vh1[1]);
                MMAH(acc[mi][3], ph[0], ph[1], ph[2], ph[3], vh1[2], vh1[3]);
            }
        }

        if (jt < 63) CP_WAIT0();
        __syncthreads();
    }

    // softmax denominators (x256 scale cancels: numerator carries it too)
    lpart[jh*64 + il] = psum;
    __syncthreads();
    if (tid < 64) sLinv[tid] = 1.0f / (lpart[tid] + lpart[64 + tid]);
    __syncthreads();

    // epilogue: /l + bias, ELU, gated residual
    const int rL = lane >> 2, cL = (lane & 3) * 2;
    #pragma unroll
    for (int mi = 0; mi < 4; mi++) {
        const float linv0 = sLinv[mi*16 + rL];
        const float linv1 = sLinv[mi*16 + rL + 8];
        #pragma unroll
        for (int ni = 0; ni < 4; ni++) {
            const int cb = wid*32 + ni*8 + cL;       // 0..127 within head
            const int col = h*128 + cb;
            const float b0 = bias[cb], b1 = bias[cb + 1];
            #pragma unroll
            for (int half = 0; half < 2; half++) {
                const int nrow = i0 + mi*16 + rL + half*8;
                const float linv = half ? linv1 : linv0;
                const size_t base = ((size_t)(b*2048) + nrow)*768 + col;
                const float2 x = *(const float2*)(feat_in + base);
                const float2 g = *(const float2*)(g_gate + base);
                float fo0 = acc[mi][ni][half*2+0]*linv + b0;
                float fo1 = acc[mi][ni][half*2+1]*linv + b1;
                const float e0 = (fo0 > 0.f) ? fo0 : expm1f(fo0);
                const float e1 = (fo1 > 0.f) ? fo1 : expm1f(fo1);
                *(float2*)(out + base) =
                    make_float2(x.x + g.x*(e0 - x.x), x.y + g.y*(e1 - x.y));
            }
        }
    }
}

extern "C" void kernel_launch(void* const* d_in, const int* in_sizes, int n_in,
                              void* d_out, int out_size) {
    (void)in_sizes; (void)n_in; (void)out_size;
    const float* feat_in = (const float*)d_in[0];
    const int*   adj     = (const int*)d_in[1];
    const float* W       = (const float*)d_in[2];
    const float* bvec    = (const float*)d_in[3];
    const float* w_src   = (const float*)d_in[4];
    const float* w_dst   = (const float*)d_in[5];
    const float* H_w     = (const float*)d_in[6];
    const float* H_b     = (const float*)d_in[7];
    float* out = (float*)d_out;

    cudaFuncSetAttribute(attn_kernel,
                         cudaFuncAttributeMaxDynamicSharedMemorySize, ATTN_SMEM_BYTES);
    cudaFuncSetAttribute(proj_mma,
                         cudaFuncAttributeMaxDynamicSharedMemorySize, PROJ_SMEM_BYTES);

    cvtX_kernel<<<6144, 256>>>(feat_in);
    buildB_kernel<<<4608, 256>>>(W, H_w);
    adjpack_kernel<<<16384, 256>>>(adj);
    proj_mma<<<dim3(12, 64), 256, PROJ_SMEM_BYTES>>>(H_b, w_src, w_dst);
    attn_kernel<<<dim3(32, 6, 4), 128, ATTN_SMEM_BYTES>>>(feat_in, bvec, out);
}